// round 14
// baseline (speedup 1.0000x reference)
#include <cuda_runtime.h>
#include <cuda_bf16.h>
#include <math.h>
#include <stdint.h>

typedef __nv_bfloat16 bf16;

// ---------------- problem constants ----------------
#define S_LEN   2048
#define BATCH   2
#define M_ROWS  4096
#define DIM_    2048
#define QL      1536
#define NH_     16
#define QK_     192
#define NOPE_   128
#define ROPE_D  64
#define VDIM_   128
#define KVL     512
#define KVD_    576
#define NQK     (NH_*QK_)            // 3072
#define NKV     (NH_*(NOPE_+VDIM_))  // 4096
#define EPS_    1.1920929e-07f
#define PITCH   24                   // gemm smem pitch (bf16)
#define QP      200                  // flash Q/K smem pitch (bf16)
#define VP      136                  // flash V smem pitch (bf16)
#define SPLIT_CH 8192                // float4 units per trailing split block

// ---------------- scratch ----------------
__device__ float g_qmid [(size_t)M_ROWS * QL];
__device__ float g_kvd  [(size_t)M_ROWS * KVD_];

__device__ bf16 g_xh [(size_t)M_ROWS*DIM_],  g_xl [(size_t)M_ROWS*DIM_];
__device__ bf16 g_qlh[(size_t)M_ROWS*QL],    g_qll[(size_t)M_ROWS*QL];
__device__ bf16 g_klh[(size_t)M_ROWS*KVL],   g_kll[(size_t)M_ROWS*KVL];
__device__ bf16 g_Qzh[(size_t)BATCH*NH_*S_LEN*QK_],  g_Qzl[(size_t)BATCH*NH_*S_LEN*QK_];
__device__ bf16 g_Kfh[(size_t)BATCH*NH_*S_LEN*QK_],  g_Kfl[(size_t)BATCH*NH_*S_LEN*QK_];
__device__ bf16 g_Vzh[(size_t)BATCH*NH_*S_LEN*VDIM_],g_Vzl[(size_t)BATCH*NH_*S_LEN*VDIM_];
__device__ bf16 g_Oh [(size_t)M_ROWS*DIM_], g_Ol [(size_t)M_ROWS*DIM_];
__device__ bf16 g_Wqdh[(size_t)QL*DIM_],   g_Wqdl[(size_t)QL*DIM_];
__device__ bf16 g_Wquh[(size_t)NQK*QL],    g_Wqul[(size_t)NQK*QL];
__device__ bf16 g_Wkdh[(size_t)KVD_*DIM_], g_Wkdl[(size_t)KVD_*DIM_];
__device__ bf16 g_Wkuh[(size_t)NKV*KVL],   g_Wkul[(size_t)NKV*KVL];
__device__ bf16 g_Woh [(size_t)DIM_*DIM_], g_Wol [(size_t)DIM_*DIM_];

// ---------------- PTX helpers ----------------
__device__ __forceinline__ uint32_t smem_u32(const void* p) {
    uint32_t a;
    asm("{ .reg .u64 t; cvta.to.shared.u64 t, %1; cvt.u32.u64 %0, t; }"
        : "=r"(a) : "l"(p));
    return a;
}
// L2-only staging copy: data is consumed once from smem; do NOT pollute L1.
__device__ __forceinline__ void cp_async16(uint32_t saddr, const void* g, int sz) {
    asm volatile("cp.async.cg.shared.global [%0], [%1], 16, %2;\n"
                 :: "r"(saddr), "l"(g), "r"(sz));
}
__device__ __forceinline__ void cp_commit() { asm volatile("cp.async.commit_group;\n"); }
template<int N> __device__ __forceinline__ void cp_wait() {
    asm volatile("cp.async.wait_group %0;\n" :: "n"(N));
}
__device__ __forceinline__ void ldsm4(uint32_t a[4], uint32_t addr) {
    asm volatile("ldmatrix.sync.aligned.m8n8.x4.shared.b16 {%0,%1,%2,%3}, [%4];\n"
                 : "=r"(a[0]), "=r"(a[1]), "=r"(a[2]), "=r"(a[3]) : "r"(addr));
}
__device__ __forceinline__ void ldsm4t(uint32_t a[4], uint32_t addr) {
    asm volatile("ldmatrix.sync.aligned.m8n8.x4.trans.shared.b16 {%0,%1,%2,%3}, [%4];\n"
                 : "=r"(a[0]), "=r"(a[1]), "=r"(a[2]), "=r"(a[3]) : "r"(addr));
}
__device__ __forceinline__ void ldsm2(uint32_t b[2], uint32_t addr) {
    asm volatile("ldmatrix.sync.aligned.m8n8.x2.shared.b16 {%0,%1}, [%2];\n"
                 : "=r"(b[0]), "=r"(b[1]) : "r"(addr));
}
__device__ __forceinline__ void mma16816(float c[4], const uint32_t a[4], const uint32_t b[2]) {
    asm volatile(
        "mma.sync.aligned.m16n8k16.row.col.f32.bf16.bf16.f32 "
        "{%0,%1,%2,%3}, {%4,%5,%6,%7}, {%8,%9}, {%0,%1,%2,%3};\n"
        : "+f"(c[0]), "+f"(c[1]), "+f"(c[2]), "+f"(c[3])
        : "r"(a[0]), "r"(a[1]), "r"(a[2]), "r"(a[3]), "r"(b[0]), "r"(b[1]));
}
__device__ __forceinline__ void split1(float v, bf16& h, bf16& l) {
    h = __float2bfloat16(v);
    l = __float2bfloat16(v - __bfloat162float(h));
}
__device__ __forceinline__ void split2(float a, float b, uint32_t& h, uint32_t& l) {
    __nv_bfloat162 hh = __floats2bfloat162_rn(a, b);
    float ra = a - __bfloat162float(hh.x);
    float rb = b - __bfloat162float(hh.y);
    __nv_bfloat162 ll = __floats2bfloat162_rn(ra, rb);
    h = *reinterpret_cast<uint32_t*>(&hh);
    l = *reinterpret_cast<uint32_t*>(&ll);
}

// ---------------- multi-job split-bf16 tensor GEMM + trailing split blocks --
struct GemmJob {
    const bf16 *Ah, *Al, *Bh, *Bl;
    const float* bias;
    float* C;
    bf16 *P1h, *P1l, *P2h, *P2l;
    int N, K, lda, ldb, ldc;
    int ntx;
    int epi;
    int tile_off;
};
struct GemmJobs {
    GemmJob j[2];
    int njobs;
    const float* freqs;
    float scale;
    // trailing fp32->bf16 split work (fills tail-wave idle slots)
    int split_off;               // first bid of split work (>= total gemm tiles)
    int nsplit;                  // segments (<=3)
    const float* ssrc[3];
    bf16 *shi[3], *slo[3];
    long long soff[4];           // prefix offsets in float4 units
};

__global__ void __launch_bounds__(256, 2)
mma_gemm_multi(GemmJobs JB)
{
    __shared__ bf16 sm[2][4][128][PITCH];

    int bid = blockIdx.x;
    // ---- trailing split blocks ----
    if (bid >= JB.split_off) {
        long long base = (long long)(bid - JB.split_off) * SPLIT_CH;
        const long long total = JB.soff[JB.nsplit];
        #pragma unroll 4
        for (int it = 0; it < SPLIT_CH / 256; it++) {
            long long idx = base + it * 256 + threadIdx.x;
            if (idx >= total) return;
            int j = 0;
            #pragma unroll
            for (int t = 1; t < 3; t++)
                if (t < JB.nsplit && idx >= JB.soff[t]) j = t;
            long long i = idx - JB.soff[j];
            float4 v = reinterpret_cast<const float4*>(JB.ssrc[j])[i];
            float f[4] = {v.x, v.y, v.z, v.w};
            union { bf16 b[4]; uint2 u; } H, L;
            #pragma unroll
            for (int k = 0; k < 4; k++) split1(f[k], H.b[k], L.b[k]);
            reinterpret_cast<uint2*>(JB.shi[j])[i] = H.u;
            reinterpret_cast<uint2*>(JB.slo[j])[i] = L.u;
        }
        return;
    }

    const int jidx = (JB.njobs > 1 && bid >= JB.j[1].tile_off) ? 1 : 0;
    const GemmJob& J = JB.j[jidx];
    bid -= J.tile_off;

    const int m0 = (bid / J.ntx) * 128, n0 = (bid % J.ntx) * 128;
    const int N = J.N, K = J.K, lda = J.lda, ldb = J.ldb;
    const int nk = K >> 4;
    const int tid = threadIdx.x, lane = tid & 31, warp = tid >> 5;
    const int wm = (warp >> 2) * 64, wn = (warp & 3) * 32;
    const int lr = tid >> 1, seg = tid & 1;
    const uint32_t smbase = (uint32_t)__cvta_generic_to_shared(&sm[0][0][0][0]);

    float acc[4][4][4];
    #pragma unroll
    for (int i = 0; i < 4; i++)
        #pragma unroll
        for (int j = 0; j < 4; j++)
            #pragma unroll
            for (int r = 0; r < 4; r++) acc[i][j][r] = 0.f;

    auto issue = [&](int st, int k0) {
        const bf16* ga0 = J.Ah + (size_t)(m0 + lr) * lda + k0 + seg * 8;
        const bf16* ga1 = J.Al + (size_t)(m0 + lr) * lda + k0 + seg * 8;
        cp_async16(smbase + ((((st*4+0)*128 + lr)*PITCH + seg*8) << 1), ga0, 16);
        cp_async16(smbase + ((((st*4+1)*128 + lr)*PITCH + seg*8) << 1), ga1, 16);
        int rr = n0 + lr;
        int sz = (rr < N) ? 16 : 0;
        int rc = (rr < N) ? rr : 0;
        const bf16* gb0 = J.Bh + (size_t)rc * ldb + k0 + seg * 8;
        const bf16* gb1 = J.Bl + (size_t)rc * ldb + k0 + seg * 8;
        cp_async16(smbase + ((((st*4+2)*128 + lr)*PITCH + seg*8) << 1), gb0, sz);
        cp_async16(smbase + ((((st*4+3)*128 + lr)*PITCH + seg*8) << 1), gb1, sz);
    };

    auto compute = [&](int st) {
        uint32_t af[4][2][4], bfr[4][2][2];
        #pragma unroll
        for (int mi = 0; mi < 4; mi++)
            #pragma unroll
            for (int p = 0; p < 2; p++) {
                int row = wm + mi * 16 + (lane & 15);
                uint32_t ad = smbase + ((((st*4+p)*128 + row)*PITCH + (lane >> 4)*8) << 1);
                ldsm4(af[mi][p], ad);
            }
        #pragma unroll
        for (int ni = 0; ni < 4; ni++)
            #pragma unroll
            for (int p = 0; p < 2; p++) {
                int row = wn + ni * 8 + (lane & 7);
                uint32_t ad = smbase + ((((st*4+2+p)*128 + row)*PITCH + ((lane & 8) ? 8 : 0)) << 1);
                ldsm2(bfr[ni][p], ad);
            }
        #pragma unroll
        for (int mi = 0; mi < 4; mi++)
            #pragma unroll
            for (int ni = 0; ni < 4; ni++) {
                mma16816(acc[mi][ni], af[mi][0], bfr[ni][0]);
                mma16816(acc[mi][ni], af[mi][0], bfr[ni][1]);
                mma16816(acc[mi][ni], af[mi][1], bfr[ni][0]);
            }
    };

    issue(0, 0); cp_commit();
    for (int i = 0; i < nk; i++) {
        int cur = i & 1;
        if (i + 1 < nk) { issue(cur ^ 1, (i + 1) << 4); cp_commit(); cp_wait<1>(); }
        else            { cp_wait<0>(); }
        __syncthreads();
        compute(cur);
        __syncthreads();
    }

    const int g = lane >> 2, tg = lane & 3;
    const int epi = J.epi;
    #pragma unroll
    for (int mi = 0; mi < 4; mi++) {
        const int rbase = m0 + wm + mi * 16 + g;
        #pragma unroll
        for (int ni = 0; ni < 4; ni++) {
            int c0 = n0 + wn + ni * 8 + 2 * tg;
            float bv0 = 0.f, bv1 = 0.f;
            if (J.bias) {
                if (c0 < N)     bv0 = J.bias[c0];
                if (c0 + 1 < N) bv1 = J.bias[c0 + 1];
            }
            #pragma unroll
            for (int half = 0; half < 2; half++) {
                const int r = rbase + half * 8;
                float v0 = acc[mi][ni][half * 2]     + bv0;
                float v1 = acc[mi][ni][half * 2 + 1] + bv1;
                if (epi == 0) {
                    long long rr = r;
                    if (c0 < N)     J.C[rr * J.ldc + c0]     = v0;
                    if (c0 + 1 < N) J.C[rr * J.ldc + c0 + 1] = v1;
                } else {
                    const int s = r & (S_LEN - 1), zb = r >> 11;
                    if (epi == 1) {
                        int h = c0 / QK_, d = c0 % QK_;
                        float y0 = v0, y1 = v1;
                        if (d >= NOPE_) {
                            int dp = (d - NOPE_) >> 1;
                            float f = JB.freqs[s * (ROPE_D / 2) + dp];
                            float cc = cosf(f), ss = sinf(f);
                            y0 = v0 * cc - v1 * ss;
                            y1 = v0 * ss + v1 * cc;
                        }
                        y0 *= JB.scale; y1 *= JB.scale;
                        uint32_t hh, ll;
                        split2(y0, y1, hh, ll);
                        size_t o = ((size_t)(zb * NH_ + h) * S_LEN + s) * QK_ + d;
                        *reinterpret_cast<uint32_t*>(J.P1h + o) = hh;
                        *reinterpret_cast<uint32_t*>(J.P1l + o) = ll;
                    } else {
                        int h = c0 >> 8, d = c0 & 255;
                        uint32_t hh, ll;
                        split2(v0, v1, hh, ll);
                        if (d < NOPE_) {
                            size_t o = ((size_t)(zb * NH_ + h) * S_LEN + s) * QK_ + d;
                            *reinterpret_cast<uint32_t*>(J.P1h + o) = hh;
                            *reinterpret_cast<uint32_t*>(J.P1l + o) = ll;
                        } else {
                            size_t o = ((size_t)(zb * NH_ + h) * S_LEN + s) * VDIM_ + (d - NOPE_);
                            *reinterpret_cast<uint32_t*>(J.P2h + o) = hh;
                            *reinterpret_cast<uint32_t*>(J.P2l + o) = ll;
                        }
                    }
                }
            }
        }
    }
}

// ---------------- fused flash attention, pipelined loads (round-11) --------
__global__ void __launch_bounds__(256, 1)
flash_kernel(const bf16* __restrict__ Qh, const bf16* __restrict__ Ql,
             const bf16* __restrict__ Kh, const bf16* __restrict__ Kl,
             const bf16* __restrict__ Vh, const bf16* __restrict__ Vl,
             bf16* __restrict__ Oh, bf16* __restrict__ Ol)
{
    extern __shared__ bf16 fs[];
    bf16* Qhs = fs;
    bf16* Qls = Qhs + 128 * QP;
    bf16* Khs = Qls + 128 * QP;
    bf16* Kls = Khs + 64 * QP;
    bf16* Vst = Kls + 64 * QP;     // Vh0, Vl0, Vh1, Vl1

    const int z = blockIdx.y, zb = z >> 4, zh = z & 15;
    const int mt = (int)gridDim.x - 1 - (int)blockIdx.x;
    const int m0 = mt * 128;
    const int tid = threadIdx.x, lane = tid & 31, warp = tid >> 5;
    const int g = lane >> 2, tg = lane & 3;
    const int wr = warp * 16;

    const uint32_t sQh = smem_u32(Qhs), sQl = smem_u32(Qls);
    const uint32_t sKh = smem_u32(Khs), sKl = smem_u32(Kls);
    const uint32_t sV0 = smem_u32(Vst);
    const uint32_t VSTRIDE = 64 * VP * 2;

    const size_t qzb = (size_t)z * S_LEN * QK_;
    const size_t vzb = (size_t)z * S_LEN * VDIM_;

    auto issue_K = [&](int k0) {
        for (int i = tid; i < 64 * 24; i += 256) {
            int r = i / 24, c = (i % 24) * 8;
            size_t go = qzb + (size_t)(k0 + r) * QK_ + c;
            uint32_t so = (uint32_t)((r * QP + c) * 2);
            cp_async16(sKh + so, Kh + go, 16);
            cp_async16(sKl + so, Kl + go, 16);
        }
    };
    auto issue_V = [&](int k0, int stage) {
        uint32_t base = sV0 + (uint32_t)stage * 2 * VSTRIDE;
        for (int i = tid; i < 64 * 16; i += 256) {
            int r = i / 16, c = (i % 16) * 8;
            size_t go = vzb + (size_t)(k0 + r) * VDIM_ + c;
            uint32_t so = (uint32_t)((r * VP + c) * 2);
            cp_async16(base + so, Vh + go, 16);
            cp_async16(base + VSTRIDE + so, Vl + go, 16);
        }
    };

    for (int i = tid; i < 128 * 24; i += 256) {
        int r = i / 24, c = (i % 24) * 8;
        size_t go = qzb + (size_t)(m0 + r) * QK_ + c;
        uint32_t so = (uint32_t)((r * QP + c) * 2);
        cp_async16(sQh + so, Qh + go, 16);
        cp_async16(sQl + so, Ql + go, 16);
    }
    cp_commit();
    issue_K(0);  cp_commit();
    issue_V(0, 0); cp_commit();

    float mr0 = -1e30f, mr1 = -1e30f, lr0 = 0.f, lr1 = 0.f;
    float oacc[16][4];
    #pragma unroll
    for (int i = 0; i < 16; i++)
        #pragma unroll
        for (int j = 0; j < 4; j++) oacc[i][j] = 0.f;

    const int nkt = (m0 + 128) / 64;
    for (int kt = 0; kt < nkt; kt++) {
        const int k0 = kt * 64;
        const int cur = kt & 1;

        __syncthreads();                      // sync1: PV readers of stage cur^1 done
        if (kt + 1 < nkt) issue_V((kt + 1) * 64, cur ^ 1);
        cp_commit();
        if (kt + 1 < nkt) cp_wait<1>();
        else             cp_wait<0>();
        __syncthreads();                      // sync2

        float sacc[8][4];
        #pragma unroll
        for (int i = 0; i < 8; i++)
            #pragma unroll
            for (int j = 0; j < 4; j++) sacc[i][j] = 0.f;

        #pragma unroll
        for (int ks = 0; ks < 12; ks++) {
            uint32_t ah[4], al[4];
            uint32_t aoff = (uint32_t)(((wr + (lane & 15)) * QP + ks * 16 + (lane >> 4) * 8) * 2);
            ldsm4(ah, sQh + aoff);
            ldsm4(al, sQl + aoff);
            #pragma unroll
            for (int np = 0; np < 4; np++) {
                uint32_t kh4[4], kl4[4];
                uint32_t boff = (uint32_t)(((np * 16 + (lane & 15)) * QP + ks * 16 + (lane >> 4) * 8) * 2);
                ldsm4(kh4, sKh + boff);
                ldsm4(kl4, sKl + boff);
                uint32_t b0h[2] = {kh4[0], kh4[2]}, b1h[2] = {kh4[1], kh4[3]};
                uint32_t b0l[2] = {kl4[0], kl4[2]}, b1l[2] = {kl4[1], kl4[3]};
                mma16816(sacc[2*np],   ah, b0h);
                mma16816(sacc[2*np],   ah, b0l);
                mma16816(sacc[2*np],   al, b0h);
                mma16816(sacc[2*np+1], ah, b1h);
                mma16816(sacc[2*np+1], ah, b1l);
                mma16816(sacc[2*np+1], al, b1h);
            }
        }

        __syncthreads();                      // sync3: K readers done
        if (kt + 1 < nkt) issue_K((kt + 1) * 64);
        cp_commit();

        if (k0 + 63 > m0) {
            int r0 = m0 + wr + g, r1 = r0 + 8;
            #pragma unroll
            for (int ni = 0; ni < 8; ni++) {
                int c0 = k0 + ni * 8 + 2 * tg;
                if (c0     > r0) sacc[ni][0] = -1e30f;
                if (c0 + 1 > r0) sacc[ni][1] = -1e30f;
                if (c0     > r1) sacc[ni][2] = -1e30f;
                if (c0 + 1 > r1) sacc[ni][3] = -1e30f;
            }
        }

        float mx0 = -1e30f, mx1 = -1e30f;
        #pragma unroll
        for (int ni = 0; ni < 8; ni++) {
            mx0 = fmaxf(mx0, fmaxf(sacc[ni][0], sacc[ni][1]));
            mx1 = fmaxf(mx1, fmaxf(sacc[ni][2], sacc[ni][3]));
        }
        mx0 = fmaxf(mx0, __shfl_xor_sync(0xffffffffu, mx0, 1));
        mx0 = fmaxf(mx0, __shfl_xor_sync(0xffffffffu, mx0, 2));
        mx1 = fmaxf(mx1, __shfl_xor_sync(0xffffffffu, mx1, 1));
        mx1 = fmaxf(mx1, __shfl_xor_sync(0xffffffffu, mx1, 2));
        float nm0 = fmaxf(mr0, mx0), nm1 = fmaxf(mr1, mx1);
        float al0 = __expf(mr0 - nm0), al1 = __expf(mr1 - nm1);
        mr0 = nm0; mr1 = nm1;
        float s0 = 0.f, s1 = 0.f;
        #pragma unroll
        for (int ni = 0; ni < 8; ni++) {
            sacc[ni][0] = __expf(sacc[ni][0] - nm0);
            sacc[ni][1] = __expf(sacc[ni][1] - nm0);
            sacc[ni][2] = __expf(sacc[ni][2] - nm1);
            sacc[ni][3] = __expf(sacc[ni][3] - nm1);
            s0 += sacc[ni][0] + sacc[ni][1];
            s1 += sacc[ni][2] + sacc[ni][3];
        }
        s0 += __shfl_xor_sync(0xffffffffu, s0, 1);
        s0 += __shfl_xor_sync(0xffffffffu, s0, 2);
        s1 += __shfl_xor_sync(0xffffffffu, s1, 1);
        s1 += __shfl_xor_sync(0xffffffffu, s1, 2);
        lr0 = lr0 * al0 + s0;
        lr1 = lr1 * al1 + s1;
        #pragma unroll
        for (int i = 0; i < 16; i++) {
            oacc[i][0] *= al0; oacc[i][1] *= al0;
            oacc[i][2] *= al1; oacc[i][3] *= al1;
        }

        const uint32_t sVh = sV0 + (uint32_t)cur * 2 * VSTRIDE;
        const uint32_t sVl = sVh + VSTRIDE;
        #pragma unroll
        for (int kk = 0; kk < 4; kk++) {
            uint32_t pah[4], pal[4];
            split2(sacc[2*kk][0],   sacc[2*kk][1],   pah[0], pal[0]);
            split2(sacc[2*kk][2],   sacc[2*kk][3],   pah[1], pal[1]);
            split2(sacc[2*kk+1][0], sacc[2*kk+1][1], pah[2], pal[2]);
            split2(sacc[2*kk+1][2], sacc[2*kk+1][3], pah[3], pal[3]);
            #pragma unroll
            for (int np = 0; np < 8; np++) {
                uint32_t vh4[4], vl4[4];
                uint32_t voff = (uint32_t)(((kk * 16 + (lane & 15)) * VP + np * 16 + (lane >> 4) * 8) * 2);
                ldsm4t(vh4, sVh + voff);
                ldsm4t(vl4, sVl + voff);
                uint32_t bh0[2] = {vh4[0], vh4[1]}, bh1[2] = {vh4[2], vh4[3]};
                uint32_t bl0[2] = {vl4[0], vl4[1]}, bl1[2] = {vl4[2], vl4[3]};
                mma16816(oacc[2*np],   pah, bh0);
                mma16816(oacc[2*np],   pah, bl0);
                mma16816(oacc[2*np],   pal, bh0);
                mma16816(oacc[2*np+1], pah, bh1);
                mma16816(oacc[2*np+1], pah, bl1);
                mma16816(oacc[2*np+1], pal, bh1);
            }
        }
    }

    float i0 = 1.f / lr0, i1 = 1.f / lr1;
    size_t row0 = (size_t)(zb * S_LEN + m0 + wr + g) * DIM_ + zh * VDIM_;
    size_t row1 = row0 + (size_t)8 * DIM_;
    #pragma unroll
    for (int ni = 0; ni < 16; ni++) {
        int d = ni * 8 + 2 * tg;
        uint32_t h0, l0, h1, l1;
        split2(oacc[ni][0] * i0, oacc[ni][1] * i0, h0, l0);
        split2(oacc[ni][2] * i1, oacc[ni][3] * i1, h1, l1);
        *reinterpret_cast<uint32_t*>(Oh + row0 + d) = h0;
        *reinterpret_cast<uint32_t*>(Ol + row0 + d) = l0;
        *reinterpret_cast<uint32_t*>(Oh + row1 + d) = h1;
        *reinterpret_cast<uint32_t*>(Ol + row1 + d) = l1;
    }
}

// ---------------- multi-segment fp32 -> (hi,lo) split (x + down weights) ----
struct SplitJobs {
    const float* src[3];
    bf16* hi[3];
    bf16* lo[3];
    long long off[4];
};
__global__ void __launch_bounds__(256)
split_multi_kernel(SplitJobs J)
{
    long long idx = (long long)blockIdx.x * 256 + threadIdx.x;
    if (idx >= J.off[3]) return;
    int j = 0;
    #pragma unroll
    for (int t = 1; t < 3; t++) if (idx >= J.off[t]) j = t;
    long long i = idx - J.off[j];
    float4 v = reinterpret_cast<const float4*>(J.src[j])[i];
    float f[4] = {v.x, v.y, v.z, v.w};
    union { bf16 b[4]; uint2 u; } H, L;
    #pragma unroll
    for (int k = 0; k < 4; k++) split1(f[k], H.b[k], L.b[k]);
    reinterpret_cast<uint2*>(J.hi[j])[i] = H.u;
    reinterpret_cast<uint2*>(J.lo[j])[i] = L.u;
}

// ---------------- merged RMSNorm (q / kv rows) + k_rope blocks ----------------
// blocks [0, M_ROWS)            : q rmsnorm+split
// blocks [M_ROWS, 2*M_ROWS)     : kv rmsnorm+split
// blocks [2*M_ROWS, +512)       : k_rope (256 elems each)
__global__ void __launch_bounds__(256)
norm_rope_kernel(const float* __restrict__ qin, const float* __restrict__ qw,
                 bf16* __restrict__ qh, bf16* __restrict__ ql,
                 const float* __restrict__ kin, const float* __restrict__ kw,
                 bf16* __restrict__ kh, bf16* __restrict__ kl,
                 const float* __restrict__ freqs,
                 bf16* __restrict__ Kfh, bf16* __restrict__ Kfl)
{
    long long blk = blockIdx.x;
    if (blk >= 2 * M_ROWS) {
        // ---- k_rope ----
        int idx = (int)(blk - 2 * M_ROWS) * 256 + threadIdx.x;
        const int total = M_ROWS * (ROPE_D / 2);
        if (idx >= total) return;
        int dp = idx % (ROPE_D / 2);
        int m  = idx / (ROPE_D / 2);
        int s  = m & (S_LEN - 1);
        int zb = m >> 11;
        float f = freqs[s * (ROPE_D / 2) + dp];
        float c = cosf(f), sn = sinf(f);
        float x0 = kin[(size_t)m * KVD_ + KVL + 2 * dp];
        float x1 = kin[(size_t)m * KVD_ + KVL + 2 * dp + 1];
        float y0 = x0 * c - x1 * sn;
        float y1 = x0 * sn + x1 * c;
        uint32_t hh, ll;
        split2(y0, y1, hh, ll);
        #pragma unroll
        for (int h = 0; h < NH_; h++) {
            size_t o = ((size_t)(zb * NH_ + h) * S_LEN + s) * QK_ + NOPE_ + 2 * dp;
            *reinterpret_cast<uint32_t*>(Kfh + o) = hh;
            *reinterpret_cast<uint32_t*>(Kfl + o) = ll;
        }
        return;
    }
    const float* p; const float* w; bf16* oh; bf16* ol; int n;
    long long row = blk;
    if (row < M_ROWS) {
        p = qin + row * QL; w = qw; oh = qh + row * QL; ol = ql + row * QL;
        n = QL;
    } else {
        row -= M_ROWS;
        p = kin + row * KVD_; w = kw; oh = kh + row * KVL; ol = kl + row * KVL;
        n = KVL;
    }
    float s = 0.f;
    for (int i = threadIdx.x; i < n; i += 256) { float v = p[i]; s += v * v; }
    __shared__ float red[256];
    red[threadIdx.x] = s; __syncthreads();
    for (int st = 128; st > 0; st >>= 1) {
        if (threadIdx.x < st) red[threadIdx.x] += red[threadIdx.x + st];
        __syncthreads();
    }
    float scale = rsqrtf(red[0] / (float)n + EPS_);
    for (int i = threadIdx.x; i < n; i += 256) {
        float v = p[i] * scale * w[i];
        split1(v, oh[i], ol[i]);
    }
}

// ---------------- host ----------------
extern "C" void kernel_launch(void* const* d_in, const int* in_sizes, int n_in,
                              void* d_out, int out_size)
{
    (void)in_sizes; (void)n_in; (void)out_size;
    const float* x        = (const float*)d_in[0];
    const float* freqs    = (const float*)d_in[1];
    const float* Wq_down  = (const float*)d_in[3];
    const float* bq_down  = (const float*)d_in[4];
    const float* q_norm   = (const float*)d_in[5];
    const float* Wq_up    = (const float*)d_in[6];
    const float* bq_up    = (const float*)d_in[7];
    const float* Wkv_down = (const float*)d_in[8];
    const float* bkv_down = (const float*)d_in[9];
    const float* kv_norm  = (const float*)d_in[10];
    const float* Wkv_up   = (const float*)d_in[11];
    const float* bkv_up   = (const float*)d_in[12];
    const float* Wo       = (const float*)d_in[13];
    const float* bo       = (const float*)d_in[14];
    float* out = (float*)d_out;

    void* p;
    #define SYM(var, sym, T) cudaGetSymbolAddress(&p, sym); T* var = (T*)p
    SYM(qmid,  g_qmid,  float);  SYM(kvd,   g_kvd,   float);
    SYM(xh,  g_xh,  bf16); SYM(xl,  g_xl,  bf16);
    SYM(qlh, g_qlh, bf16); SYM(qll, g_qll, bf16);
    SYM(klh, g_klh, bf16); SYM(kll, g_kll, bf16);
    SYM(Qzh, g_Qzh, bf16); SYM(Qzl, g_Qzl, bf16);
    SYM(Kfh, g_Kfh, bf16); SYM(Kfl, g_Kfl, bf16);
    SYM(Vzh, g_Vzh, bf16); SYM(Vzl, g_Vzl, bf16);
    SYM(Oh,  g_Oh,  bf16); SYM(Ol,  g_Ol,  bf16);
    SYM(Wqdh, g_Wqdh, bf16); SYM(Wqdl, g_Wqdl, bf16);
    SYM(Wquh, g_Wquh, bf16); SYM(Wqul, g_Wqul, bf16);
    SYM(Wkdh, g_Wkdh, bf16); SYM(Wkdl, g_Wkdl, bf16);
    SYM(Wkuh, g_Wkuh, bf16); SYM(Wkul, g_Wkul, bf16);
    SYM(Woh,  g_Woh,  bf16); SYM(Wol,  g_Wol,  bf16);
    #undef SYM

    const float scale = 1.0f / sqrtf((float)QK_);
    const int FLASH_SMEM = (2 * 128 * QP + 2 * 64 * QP + 4 * 64 * VP) * 2;  // 223232 B
    cudaFuncSetAttribute(flash_kernel, cudaFuncAttributeMaxDynamicSharedMemorySize, FLASH_SMEM);

    // 0) splits needed by the down launch: x, Wq_down, Wkv_down
    SplitJobs SJ;
    SJ.src[0] = x;        SJ.hi[0] = xh;   SJ.lo[0] = xl;
    SJ.src[1] = Wq_down;  SJ.hi[1] = Wqdh; SJ.lo[1] = Wqdl;
    SJ.src[2] = Wkv_down; SJ.hi[2] = Wkdh; SJ.lo[2] = Wkdl;
    long long n4a[3] = {
        (long long)M_ROWS*DIM_/4, (long long)QL*DIM_/4, (long long)KVD_*DIM_/4 };
    SJ.off[0] = 0;
    for (int i = 0; i < 3; i++) SJ.off[i+1] = SJ.off[i] + n4a[i];
    split_multi_kernel<<<(int)((SJ.off[3] + 255) / 256), 256>>>(SJ);

    auto mkjob = [](const bf16* Ah, const bf16* Al, const bf16* Bh, const bf16* Bl,
                    const float* bias, float* C,
                    bf16* P1h, bf16* P1l, bf16* P2h, bf16* P2l,
                    int N, int K, int lda, int ldb, int ldc, int epi, int tile_off) {
        GemmJob j;
        j.Ah = Ah; j.Al = Al; j.Bh = Bh; j.Bl = Bl; j.bias = bias; j.C = C;
        j.P1h = P1h; j.P1l = P1l; j.P2h = P2h; j.P2l = P2l;
        j.N = N; j.K = K; j.lda = lda; j.ldb = ldb; j.ldc = ldc;
        j.ntx = (N + 127) / 128; j.epi = epi; j.tile_off = tile_off;
        return j;
    };

    // 1) merged down-projections + trailing up/wo weight splits
    {
        GemmJobs JB;
        JB.njobs = 2; JB.freqs = freqs; JB.scale = scale;
        JB.j[0] = mkjob(xh, xl, Wqdh, Wqdl, bq_down, qmid,
                        nullptr, nullptr, nullptr, nullptr,
                        QL, DIM_, DIM_, DIM_, QL, 0, 0);
        int t0 = (QL/128) * (M_ROWS/128);                       // 384
        JB.j[1] = mkjob(xh, xl, Wkdh, Wkdl, bkv_down, kvd,
                        nullptr, nullptr, nullptr, nullptr,
                        KVD_, DIM_, DIM_, DIM_, KVD_, 0, t0);
        int ngemm = t0 + ((KVD_+127)/128) * (M_ROWS/128);       // 544
        // trailing splits: Wq_up, Wkv_up, Wo
        JB.split_off = ngemm;
        JB.nsplit = 3;
        JB.ssrc[0] = Wq_up;  JB.shi[0] = Wquh; JB.slo[0] = Wqul;
        JB.ssrc[1] = Wkv_up; JB.shi[1] = Wkuh; JB.slo[1] = Wkul;
        JB.ssrc[2] = Wo;     JB.shi[2] = Woh;  JB.slo[2] = Wol;
        long long n4b[3] = {
            (long long)NQK*QL/4, (long long)NKV*KVL/4, (long long)DIM_*DIM_/4 };
        JB.soff[0] = 0;
        for (int i = 0; i < 3; i++) JB.soff[i+1] = JB.soff[i] + n4b[i];
        int nsb = (int)((JB.soff[3] + SPLIT_CH - 1) / SPLIT_CH);
        mma_gemm_multi<<<ngemm + nsb, 256>>>(JB);
    }
    // 2) merged rmsnorm + k_rope (one launch, disjoint block ranges)
    norm_rope_kernel<<<2 * M_ROWS + (M_ROWS*(ROPE_D/2) + 255)/256, 256>>>(
        qmid, q_norm, qlh, qll, kvd, kv_norm, klh, kll, freqs, Kfh, Kfl);
    // 3) merged up-projections: Q (768 tiles, EPI1) + KV (1024 tiles, EPI2)
    {
        GemmJobs JB;
        JB.njobs = 2; JB.freqs = freqs; JB.scale = scale;
        JB.j[0] = mkjob(qlh, qll, Wquh, Wqul, bq_up, nullptr,
                        Qzh, Qzl, nullptr, nullptr,
                        NQK, QL, QL, QL, NQK, 1, 0);
        int t0 = (NQK/128) * (M_ROWS/128);
        JB.j[1] = mkjob(klh, kll, Wkuh, Wkul, bkv_up, nullptr,
                        Kfh, Kfl, Vzh, Vzl,
                        NKV, KVL, KVL, KVL, NKV, 2, t0);
        int total = t0 + (NKV/128) * (M_ROWS/128);
        JB.split_off = 0x7fffffff; JB.nsplit = 0;
        JB.soff[0] = JB.soff[1] = JB.soff[2] = JB.soff[3] = 0;
        mma_gemm_multi<<<total, 256>>>(JB);
    }
    // 4) pipelined flash attention -> Oh/Ol
    flash_kernel<<<dim3(16, BATCH*NH_), 256, FLASH_SMEM>>>(
        Qzh, Qzl, Kfh, Kfl, Vzh, Vzl, Oh, Ol);
    // 5) out = O @ Wo^T + b
    {
        GemmJobs JB;
        JB.njobs = 1; JB.freqs = freqs; JB.scale = scale;
        JB.j[0] = mkjob(Oh, Ol, Woh, Wol, bo, out,
                        nullptr, nullptr, nullptr, nullptr,
                        DIM_, NH_*VDIM_, NH_*VDIM_, NH_*VDIM_, DIM_, 0, 0);
        JB.split_off = 0x7fffffff; JB.nsplit = 0;
        JB.soff[0] = JB.soff[1] = JB.soff[2] = JB.soff[3] = 0;
        mma_gemm_multi<<<(DIM_/128) * (M_ROWS/128), 256>>>(JB);
    }
}

// round 15
// speedup vs baseline: 1.0089x; 1.0089x over previous
#include <cuda_runtime.h>
#include <cuda_bf16.h>
#include <math.h>
#include <stdint.h>

typedef __nv_bfloat16 bf16;

// ---------------- problem constants ----------------
#define S_LEN   2048
#define BATCH   2
#define M_ROWS  4096
#define DIM_    2048
#define QL      1536
#define NH_     16
#define QK_     192
#define NOPE_   128
#define ROPE_D  64
#define VDIM_   128
#define KVL     512
#define KVD_    576
#define NQK     (NH_*QK_)            // 3072
#define NKV     (NH_*(NOPE_+VDIM_))  // 4096
#define EPS_    1.1920929e-07f
#define PITCH   24                   // gemm smem pitch (bf16)
#define QP      200                  // flash Q/K smem pitch (bf16)
#define VP      136                  // flash V smem pitch (bf16)

// ---------------- scratch ----------------
__device__ float g_qmid [(size_t)M_ROWS * QL];
__device__ float g_kvd  [(size_t)M_ROWS * KVD_];

__device__ bf16 g_xh [(size_t)M_ROWS*DIM_],  g_xl [(size_t)M_ROWS*DIM_];
__device__ bf16 g_qlh[(size_t)M_ROWS*QL],    g_qll[(size_t)M_ROWS*QL];
__device__ bf16 g_klh[(size_t)M_ROWS*KVL],   g_kll[(size_t)M_ROWS*KVL];
__device__ bf16 g_Qzh[(size_t)BATCH*NH_*S_LEN*QK_],  g_Qzl[(size_t)BATCH*NH_*S_LEN*QK_];
__device__ bf16 g_Kfh[(size_t)BATCH*NH_*S_LEN*QK_],  g_Kfl[(size_t)BATCH*NH_*S_LEN*QK_];
__device__ bf16 g_Vzh[(size_t)BATCH*NH_*S_LEN*VDIM_],g_Vzl[(size_t)BATCH*NH_*S_LEN*VDIM_];
__device__ bf16 g_Oh [(size_t)M_ROWS*DIM_], g_Ol [(size_t)M_ROWS*DIM_];
__device__ bf16 g_Wqdh[(size_t)QL*DIM_],   g_Wqdl[(size_t)QL*DIM_];
__device__ bf16 g_Wquh[(size_t)NQK*QL],    g_Wqul[(size_t)NQK*QL];
__device__ bf16 g_Wkdh[(size_t)KVD_*DIM_], g_Wkdl[(size_t)KVD_*DIM_];
__device__ bf16 g_Wkuh[(size_t)NKV*KVL],   g_Wkul[(size_t)NKV*KVL];
__device__ bf16 g_Woh [(size_t)DIM_*DIM_], g_Wol [(size_t)DIM_*DIM_];

// ---------------- PTX helpers ----------------
__device__ __forceinline__ uint32_t smem_u32(const void* p) {
    uint32_t a;
    asm("{ .reg .u64 t; cvta.to.shared.u64 t, %1; cvt.u32.u64 %0, t; }"
        : "=r"(a) : "l"(p));
    return a;
}
// L2-only staging copy: data is consumed once from smem; do NOT pollute L1.
__device__ __forceinline__ void cp_async16(uint32_t saddr, const void* g, int sz) {
    asm volatile("cp.async.cg.shared.global [%0], [%1], 16, %2;\n"
                 :: "r"(saddr), "l"(g), "r"(sz));
}
__device__ __forceinline__ void cp_commit() { asm volatile("cp.async.commit_group;\n"); }
template<int N> __device__ __forceinline__ void cp_wait() {
    asm volatile("cp.async.wait_group %0;\n" :: "n"(N));
}
__device__ __forceinline__ void ldsm4(uint32_t a[4], uint32_t addr) {
    asm volatile("ldmatrix.sync.aligned.m8n8.x4.shared.b16 {%0,%1,%2,%3}, [%4];\n"
                 : "=r"(a[0]), "=r"(a[1]), "=r"(a[2]), "=r"(a[3]) : "r"(addr));
}
__device__ __forceinline__ void ldsm4t(uint32_t a[4], uint32_t addr) {
    asm volatile("ldmatrix.sync.aligned.m8n8.x4.trans.shared.b16 {%0,%1,%2,%3}, [%4];\n"
                 : "=r"(a[0]), "=r"(a[1]), "=r"(a[2]), "=r"(a[3]) : "r"(addr));
}
__device__ __forceinline__ void ldsm2(uint32_t b[2], uint32_t addr) {
    asm volatile("ldmatrix.sync.aligned.m8n8.x2.shared.b16 {%0,%1}, [%2];\n"
                 : "=r"(b[0]), "=r"(b[1]) : "r"(addr));
}
__device__ __forceinline__ void mma16816(float c[4], const uint32_t a[4], const uint32_t b[2]) {
    asm volatile(
        "mma.sync.aligned.m16n8k16.row.col.f32.bf16.bf16.f32 "
        "{%0,%1,%2,%3}, {%4,%5,%6,%7}, {%8,%9}, {%0,%1,%2,%3};\n"
        : "+f"(c[0]), "+f"(c[1]), "+f"(c[2]), "+f"(c[3])
        : "r"(a[0]), "r"(a[1]), "r"(a[2]), "r"(a[3]), "r"(b[0]), "r"(b[1]));
}
__device__ __forceinline__ void split1(float v, bf16& h, bf16& l) {
    h = __float2bfloat16(v);
    l = __float2bfloat16(v - __bfloat162float(h));
}
__device__ __forceinline__ void split2(float a, float b, uint32_t& h, uint32_t& l) {
    __nv_bfloat162 hh = __floats2bfloat162_rn(a, b);
    float ra = a - __bfloat162float(hh.x);
    float rb = b - __bfloat162float(hh.y);
    __nv_bfloat162 ll = __floats2bfloat162_rn(ra, rb);
    h = *reinterpret_cast<uint32_t*>(&hh);
    l = *reinterpret_cast<uint32_t*>(&ll);
}

// ---------------- multi-job split-bf16 tensor GEMM (round-13 proven) -------
struct GemmJob {
    const bf16 *Ah, *Al, *Bh, *Bl;
    const float* bias;
    float* C;
    bf16 *P1h, *P1l, *P2h, *P2l;
    int N, K, lda, ldb, ldc;
    int ntx;
    int epi;
    int tile_off;
};
struct GemmJobs {
    GemmJob j[2];
    int njobs;
    const float* freqs;
    float scale;
};

__global__ void __launch_bounds__(256, 2)
mma_gemm_multi(GemmJobs JB)
{
    __shared__ bf16 sm[2][4][128][PITCH];

    int bid = blockIdx.x;
    const int jidx = (JB.njobs > 1 && bid >= JB.j[1].tile_off) ? 1 : 0;
    const GemmJob& J = JB.j[jidx];
    bid -= J.tile_off;

    const int m0 = (bid / J.ntx) * 128, n0 = (bid % J.ntx) * 128;
    const int N = J.N, K = J.K, lda = J.lda, ldb = J.ldb;
    const int nk = K >> 4;
    const int tid = threadIdx.x, lane = tid & 31, warp = tid >> 5;
    const int wm = (warp >> 2) * 64, wn = (warp & 3) * 32;
    const int lr = tid >> 1, seg = tid & 1;
    const uint32_t smbase = (uint32_t)__cvta_generic_to_shared(&sm[0][0][0][0]);

    float acc[4][4][4];
    #pragma unroll
    for (int i = 0; i < 4; i++)
        #pragma unroll
        for (int j = 0; j < 4; j++)
            #pragma unroll
            for (int r = 0; r < 4; r++) acc[i][j][r] = 0.f;

    auto issue = [&](int st, int k0) {
        const bf16* ga0 = J.Ah + (size_t)(m0 + lr) * lda + k0 + seg * 8;
        const bf16* ga1 = J.Al + (size_t)(m0 + lr) * lda + k0 + seg * 8;
        cp_async16(smbase + ((((st*4+0)*128 + lr)*PITCH + seg*8) << 1), ga0, 16);
        cp_async16(smbase + ((((st*4+1)*128 + lr)*PITCH + seg*8) << 1), ga1, 16);
        int rr = n0 + lr;
        int sz = (rr < N) ? 16 : 0;
        int rc = (rr < N) ? rr : 0;
        const bf16* gb0 = J.Bh + (size_t)rc * ldb + k0 + seg * 8;
        const bf16* gb1 = J.Bl + (size_t)rc * ldb + k0 + seg * 8;
        cp_async16(smbase + ((((st*4+2)*128 + lr)*PITCH + seg*8) << 1), gb0, sz);
        cp_async16(smbase + ((((st*4+3)*128 + lr)*PITCH + seg*8) << 1), gb1, sz);
    };

    auto compute = [&](int st) {
        uint32_t af[4][2][4], bfr[4][2][2];
        #pragma unroll
        for (int mi = 0; mi < 4; mi++)
            #pragma unroll
            for (int p = 0; p < 2; p++) {
                int row = wm + mi * 16 + (lane & 15);
                uint32_t ad = smbase + ((((st*4+p)*128 + row)*PITCH + (lane >> 4)*8) << 1);
                ldsm4(af[mi][p], ad);
            }
        #pragma unroll
        for (int ni = 0; ni < 4; ni++)
            #pragma unroll
            for (int p = 0; p < 2; p++) {
                int row = wn + ni * 8 + (lane & 7);
                uint32_t ad = smbase + ((((st*4+2+p)*128 + row)*PITCH + ((lane & 8) ? 8 : 0)) << 1);
                ldsm2(bfr[ni][p], ad);
            }
        #pragma unroll
        for (int mi = 0; mi < 4; mi++)
            #pragma unroll
            for (int ni = 0; ni < 4; ni++) {
                mma16816(acc[mi][ni], af[mi][0], bfr[ni][0]);
                mma16816(acc[mi][ni], af[mi][0], bfr[ni][1]);
                mma16816(acc[mi][ni], af[mi][1], bfr[ni][0]);
            }
    };

    issue(0, 0); cp_commit();
    for (int i = 0; i < nk; i++) {
        int cur = i & 1;
        if (i + 1 < nk) { issue(cur ^ 1, (i + 1) << 4); cp_commit(); cp_wait<1>(); }
        else            { cp_wait<0>(); }
        __syncthreads();
        compute(cur);
        __syncthreads();
    }

    const int g = lane >> 2, tg = lane & 3;
    const int epi = J.epi;
    #pragma unroll
    for (int mi = 0; mi < 4; mi++) {
        const int rbase = m0 + wm + mi * 16 + g;
        #pragma unroll
        for (int ni = 0; ni < 4; ni++) {
            int c0 = n0 + wn + ni * 8 + 2 * tg;
            float bv0 = 0.f, bv1 = 0.f;
            if (J.bias) {
                if (c0 < N)     bv0 = J.bias[c0];
                if (c0 + 1 < N) bv1 = J.bias[c0 + 1];
            }
            #pragma unroll
            for (int half = 0; half < 2; half++) {
                const int r = rbase + half * 8;
                float v0 = acc[mi][ni][half * 2]     + bv0;
                float v1 = acc[mi][ni][half * 2 + 1] + bv1;
                if (epi == 0) {
                    long long rr = r;
                    if (c0 < N)     J.C[rr * J.ldc + c0]     = v0;
                    if (c0 + 1 < N) J.C[rr * J.ldc + c0 + 1] = v1;
                } else {
                    const int s = r & (S_LEN - 1), zb = r >> 11;
                    if (epi == 1) {
                        int h = c0 / QK_, d = c0 % QK_;
                        float y0 = v0, y1 = v1;
                        if (d >= NOPE_) {
                            int dp = (d - NOPE_) >> 1;
                            float f = JB.freqs[s * (ROPE_D / 2) + dp];
                            float cc = cosf(f), ss = sinf(f);
                            y0 = v0 * cc - v1 * ss;
                            y1 = v0 * ss + v1 * cc;
                        }
                        y0 *= JB.scale; y1 *= JB.scale;
                        uint32_t hh, ll;
                        split2(y0, y1, hh, ll);
                        size_t o = ((size_t)(zb * NH_ + h) * S_LEN + s) * QK_ + d;
                        *reinterpret_cast<uint32_t*>(J.P1h + o) = hh;
                        *reinterpret_cast<uint32_t*>(J.P1l + o) = ll;
                    } else {
                        int h = c0 >> 8, d = c0 & 255;
                        uint32_t hh, ll;
                        split2(v0, v1, hh, ll);
                        if (d < NOPE_) {
                            size_t o = ((size_t)(zb * NH_ + h) * S_LEN + s) * QK_ + d;
                            *reinterpret_cast<uint32_t*>(J.P1h + o) = hh;
                            *reinterpret_cast<uint32_t*>(J.P1l + o) = ll;
                        } else {
                            size_t o = ((size_t)(zb * NH_ + h) * S_LEN + s) * VDIM_ + (d - NOPE_);
                            *reinterpret_cast<uint32_t*>(J.P2h + o) = hh;
                            *reinterpret_cast<uint32_t*>(J.P2l + o) = ll;
                        }
                    }
                }
            }
        }
    }
}

// ---------------- fused flash attention, pipelined loads (round-11) --------
__global__ void __launch_bounds__(256, 1)
flash_kernel(const bf16* __restrict__ Qh, const bf16* __restrict__ Ql,
             const bf16* __restrict__ Kh, const bf16* __restrict__ Kl,
             const bf16* __restrict__ Vh, const bf16* __restrict__ Vl,
             bf16* __restrict__ Oh, bf16* __restrict__ Ol)
{
    extern __shared__ bf16 fs[];
    bf16* Qhs = fs;
    bf16* Qls = Qhs + 128 * QP;
    bf16* Khs = Qls + 128 * QP;
    bf16* Kls = Khs + 64 * QP;
    bf16* Vst = Kls + 64 * QP;     // Vh0, Vl0, Vh1, Vl1

    const int z = blockIdx.y, zb = z >> 4, zh = z & 15;
    const int mt = (int)gridDim.x - 1 - (int)blockIdx.x;
    const int m0 = mt * 128;
    const int tid = threadIdx.x, lane = tid & 31, warp = tid >> 5;
    const int g = lane >> 2, tg = lane & 3;
    const int wr = warp * 16;

    const uint32_t sQh = smem_u32(Qhs), sQl = smem_u32(Qls);
    const uint32_t sKh = smem_u32(Khs), sKl = smem_u32(Kls);
    const uint32_t sV0 = smem_u32(Vst);
    const uint32_t VSTRIDE = 64 * VP * 2;

    const size_t qzb = (size_t)z * S_LEN * QK_;
    const size_t vzb = (size_t)z * S_LEN * VDIM_;

    auto issue_K = [&](int k0) {
        for (int i = tid; i < 64 * 24; i += 256) {
            int r = i / 24, c = (i % 24) * 8;
            size_t go = qzb + (size_t)(k0 + r) * QK_ + c;
            uint32_t so = (uint32_t)((r * QP + c) * 2);
            cp_async16(sKh + so, Kh + go, 16);
            cp_async16(sKl + so, Kl + go, 16);
        }
    };
    auto issue_V = [&](int k0, int stage) {
        uint32_t base = sV0 + (uint32_t)stage * 2 * VSTRIDE;
        for (int i = tid; i < 64 * 16; i += 256) {
            int r = i / 16, c = (i % 16) * 8;
            size_t go = vzb + (size_t)(k0 + r) * VDIM_ + c;
            uint32_t so = (uint32_t)((r * VP + c) * 2);
            cp_async16(base + so, Vh + go, 16);
            cp_async16(base + VSTRIDE + so, Vl + go, 16);
        }
    };

    for (int i = tid; i < 128 * 24; i += 256) {
        int r = i / 24, c = (i % 24) * 8;
        size_t go = qzb + (size_t)(m0 + r) * QK_ + c;
        uint32_t so = (uint32_t)((r * QP + c) * 2);
        cp_async16(sQh + so, Qh + go, 16);
        cp_async16(sQl + so, Ql + go, 16);
    }
    cp_commit();
    issue_K(0);  cp_commit();
    issue_V(0, 0); cp_commit();

    float mr0 = -1e30f, mr1 = -1e30f, lr0 = 0.f, lr1 = 0.f;
    float oacc[16][4];
    #pragma unroll
    for (int i = 0; i < 16; i++)
        #pragma unroll
        for (int j = 0; j < 4; j++) oacc[i][j] = 0.f;

    const int nkt = (m0 + 128) / 64;
    for (int kt = 0; kt < nkt; kt++) {
        const int k0 = kt * 64;
        const int cur = kt & 1;

        __syncthreads();                      // sync1: PV readers of stage cur^1 done
        if (kt + 1 < nkt) issue_V((kt + 1) * 64, cur ^ 1);
        cp_commit();
        if (kt + 1 < nkt) cp_wait<1>();
        else             cp_wait<0>();
        __syncthreads();                      // sync2

        float sacc[8][4];
        #pragma unroll
        for (int i = 0; i < 8; i++)
            #pragma unroll
            for (int j = 0; j < 4; j++) sacc[i][j] = 0.f;

        #pragma unroll
        for (int ks = 0; ks < 12; ks++) {
            uint32_t ah[4], al[4];
            uint32_t aoff = (uint32_t)(((wr + (lane & 15)) * QP + ks * 16 + (lane >> 4) * 8) * 2);
            ldsm4(ah, sQh + aoff);
            ldsm4(al, sQl + aoff);
            #pragma unroll
            for (int np = 0; np < 4; np++) {
                uint32_t kh4[4], kl4[4];
                uint32_t boff = (uint32_t)(((np * 16 + (lane & 15)) * QP + ks * 16 + (lane >> 4) * 8) * 2);
                ldsm4(kh4, sKh + boff);
                ldsm4(kl4, sKl + boff);
                uint32_t b0h[2] = {kh4[0], kh4[2]}, b1h[2] = {kh4[1], kh4[3]};
                uint32_t b0l[2] = {kl4[0], kl4[2]}, b1l[2] = {kl4[1], kl4[3]};
                mma16816(sacc[2*np],   ah, b0h);
                mma16816(sacc[2*np],   ah, b0l);
                mma16816(sacc[2*np],   al, b0h);
                mma16816(sacc[2*np+1], ah, b1h);
                mma16816(sacc[2*np+1], ah, b1l);
                mma16816(sacc[2*np+1], al, b1h);
            }
        }

        __syncthreads();                      // sync3: K readers done
        if (kt + 1 < nkt) issue_K((kt + 1) * 64);
        cp_commit();

        if (k0 + 63 > m0) {
            int r0 = m0 + wr + g, r1 = r0 + 8;
            #pragma unroll
            for (int ni = 0; ni < 8; ni++) {
                int c0 = k0 + ni * 8 + 2 * tg;
                if (c0     > r0) sacc[ni][0] = -1e30f;
                if (c0 + 1 > r0) sacc[ni][1] = -1e30f;
                if (c0     > r1) sacc[ni][2] = -1e30f;
                if (c0 + 1 > r1) sacc[ni][3] = -1e30f;
            }
        }

        float mx0 = -1e30f, mx1 = -1e30f;
        #pragma unroll
        for (int ni = 0; ni < 8; ni++) {
            mx0 = fmaxf(mx0, fmaxf(sacc[ni][0], sacc[ni][1]));
            mx1 = fmaxf(mx1, fmaxf(sacc[ni][2], sacc[ni][3]));
        }
        mx0 = fmaxf(mx0, __shfl_xor_sync(0xffffffffu, mx0, 1));
        mx0 = fmaxf(mx0, __shfl_xor_sync(0xffffffffu, mx0, 2));
        mx1 = fmaxf(mx1, __shfl_xor_sync(0xffffffffu, mx1, 1));
        mx1 = fmaxf(mx1, __shfl_xor_sync(0xffffffffu, mx1, 2));
        float nm0 = fmaxf(mr0, mx0), nm1 = fmaxf(mr1, mx1);
        float al0 = __expf(mr0 - nm0), al1 = __expf(mr1 - nm1);
        mr0 = nm0; mr1 = nm1;
        float s0 = 0.f, s1 = 0.f;
        #pragma unroll
        for (int ni = 0; ni < 8; ni++) {
            sacc[ni][0] = __expf(sacc[ni][0] - nm0);
            sacc[ni][1] = __expf(sacc[ni][1] - nm0);
            sacc[ni][2] = __expf(sacc[ni][2] - nm1);
            sacc[ni][3] = __expf(sacc[ni][3] - nm1);
            s0 += sacc[ni][0] + sacc[ni][1];
            s1 += sacc[ni][2] + sacc[ni][3];
        }
        s0 += __shfl_xor_sync(0xffffffffu, s0, 1);
        s0 += __shfl_xor_sync(0xffffffffu, s0, 2);
        s1 += __shfl_xor_sync(0xffffffffu, s1, 1);
        s1 += __shfl_xor_sync(0xffffffffu, s1, 2);
        lr0 = lr0 * al0 + s0;
        lr1 = lr1 * al1 + s1;
        #pragma unroll
        for (int i = 0; i < 16; i++) {
            oacc[i][0] *= al0; oacc[i][1] *= al0;
            oacc[i][2] *= al1; oacc[i][3] *= al1;
        }

        const uint32_t sVh = sV0 + (uint32_t)cur * 2 * VSTRIDE;
        const uint32_t sVl = sVh + VSTRIDE;
        #pragma unroll
        for (int kk = 0; kk < 4; kk++) {
            uint32_t pah[4], pal[4];
            split2(sacc[2*kk][0],   sacc[2*kk][1],   pah[0], pal[0]);
            split2(sacc[2*kk][2],   sacc[2*kk][3],   pah[1], pal[1]);
            split2(sacc[2*kk+1][0], sacc[2*kk+1][1], pah[2], pal[2]);
            split2(sacc[2*kk+1][2], sacc[2*kk+1][3], pah[3], pal[3]);
            #pragma unroll
            for (int np = 0; np < 8; np++) {
                uint32_t vh4[4], vl4[4];
                uint32_t voff = (uint32_t)(((kk * 16 + (lane & 15)) * VP + np * 16 + (lane >> 4) * 8) * 2);
                ldsm4t(vh4, sVh + voff);
                ldsm4t(vl4, sVl + voff);
                uint32_t bh0[2] = {vh4[0], vh4[1]}, bh1[2] = {vh4[2], vh4[3]};
                uint32_t bl0[2] = {vl4[0], vl4[1]}, bl1[2] = {vl4[2], vl4[3]};
                mma16816(oacc[2*np],   pah, bh0);
                mma16816(oacc[2*np],   pah, bl0);
                mma16816(oacc[2*np],   pal, bh0);
                mma16816(oacc[2*np+1], pah, bh1);
                mma16816(oacc[2*np+1], pah, bl1);
                mma16816(oacc[2*np+1], pal, bh1);
            }
        }
    }

    float i0 = 1.f / lr0, i1 = 1.f / lr1;
    size_t row0 = (size_t)(zb * S_LEN + m0 + wr + g) * DIM_ + zh * VDIM_;
    size_t row1 = row0 + (size_t)8 * DIM_;
    #pragma unroll
    for (int ni = 0; ni < 16; ni++) {
        int d = ni * 8 + 2 * tg;
        uint32_t h0, l0, h1, l1;
        split2(oacc[ni][0] * i0, oacc[ni][1] * i0, h0, l0);
        split2(oacc[ni][2] * i1, oacc[ni][3] * i1, h1, l1);
        *reinterpret_cast<uint32_t*>(Oh + row0 + d) = h0;
        *reinterpret_cast<uint32_t*>(Ol + row0 + d) = l0;
        *reinterpret_cast<uint32_t*>(Oh + row1 + d) = h1;
        *reinterpret_cast<uint32_t*>(Ol + row1 + d) = l1;
    }
}

// ---------------- multi-segment fp32 -> (hi,lo) split, 16B stores ----------
// Each thread handles TWO adjacent float4 (8 floats) -> one uint4 store per
// hi/lo buffer (full 128B warp coalescing). All segment sizes are even in
// float4 units, so a pair never straddles a segment boundary.
struct SplitJobs {
    const float* src[6];
    bf16* hi[6];
    bf16* lo[6];
    long long off[7];   // prefix offsets in float4 units (all even)
};
__global__ void __launch_bounds__(256)
split_multi_kernel(SplitJobs J)
{
    long long gidx = (long long)blockIdx.x * 256 + threadIdx.x;   // group of 2 float4
    if (gidx * 2 >= J.off[6]) return;
    long long idx = gidx * 2;
    int j = 0;
    #pragma unroll
    for (int t = 1; t < 6; t++) if (idx >= J.off[t]) j = t;
    long long i = idx - J.off[j];
    float4 v0 = reinterpret_cast<const float4*>(J.src[j])[i];
    float4 v1 = reinterpret_cast<const float4*>(J.src[j])[i + 1];
    float f[8] = {v0.x, v0.y, v0.z, v0.w, v1.x, v1.y, v1.z, v1.w};
    union { bf16 b[8]; uint4 u; } H, L;
    #pragma unroll
    for (int k = 0; k < 8; k++) split1(f[k], H.b[k], L.b[k]);
    reinterpret_cast<uint4*>(J.hi[j])[i >> 1] = H.u;
    reinterpret_cast<uint4*>(J.lo[j])[i >> 1] = L.u;
}

// ---------------- merged RMSNorm (q rows then kv rows) + split ----------------
__global__ void __launch_bounds__(256)
rmsnorm2_kernel(const float* __restrict__ qin, const float* __restrict__ qw,
                bf16* __restrict__ qh, bf16* __restrict__ ql,
                const float* __restrict__ kin, const float* __restrict__ kw,
                bf16* __restrict__ kh, bf16* __restrict__ kl)
{
    long long row = blockIdx.x;
    const float* p; const float* w; bf16* oh; bf16* ol; int n;
    if (row < M_ROWS) {
        p = qin + row * QL; w = qw; oh = qh + row * QL; ol = ql + row * QL;
        n = QL;
    } else {
        row -= M_ROWS;
        p = kin + row * KVD_; w = kw; oh = kh + row * KVL; ol = kl + row * KVL;
        n = KVL;
    }
    float s = 0.f;
    for (int i = threadIdx.x; i < n; i += 256) { float v = p[i]; s += v * v; }
    __shared__ float red[256];
    red[threadIdx.x] = s; __syncthreads();
    for (int st = 128; st > 0; st >>= 1) {
        if (threadIdx.x < st) red[threadIdx.x] += red[threadIdx.x + st];
        __syncthreads();
    }
    float scale = rsqrtf(red[0] / (float)n + EPS_);
    for (int i = threadIdx.x; i < n; i += 256) {
        float v = p[i] * scale * w[i];
        split1(v, oh[i], ol[i]);
    }
}

// ---------------- K rope part: rope(kvd cols 512..575) -> Kf cols 128..191 ---
__global__ void __launch_bounds__(256)
k_rope_kernel(const float* __restrict__ kvd, const float* __restrict__ freqs,
              bf16* __restrict__ Kfh, bf16* __restrict__ Kfl)
{
    int idx = blockIdx.x * 256 + threadIdx.x;
    const int total = M_ROWS * (ROPE_D / 2);
    if (idx >= total) return;
    int dp = idx % (ROPE_D / 2);
    int m  = idx / (ROPE_D / 2);
    int s  = m & (S_LEN - 1);
    int zb = m >> 11;
    float f = freqs[s * (ROPE_D / 2) + dp];
    float c = cosf(f), sn = sinf(f);
    float x0 = kvd[(size_t)m * KVD_ + KVL + 2 * dp];
    float x1 = kvd[(size_t)m * KVD_ + KVL + 2 * dp + 1];
    float y0 = x0 * c - x1 * sn;
    float y1 = x0 * sn + x1 * c;
    bf16 h0, l0, h1, l1;
    split1(y0, h0, l0);
    split1(y1, h1, l1);
    #pragma unroll
    for (int h = 0; h < NH_; h++) {
        size_t o = ((size_t)(zb * NH_ + h) * S_LEN + s) * QK_ + NOPE_ + 2 * dp;
        Kfh[o] = h0; Kfl[o] = l0;
        Kfh[o + 1] = h1; Kfl[o + 1] = l1;
    }
}

// ---------------- host ----------------
extern "C" void kernel_launch(void* const* d_in, const int* in_sizes, int n_in,
                              void* d_out, int out_size)
{
    (void)in_sizes; (void)n_in; (void)out_size;
    const float* x        = (const float*)d_in[0];
    const float* freqs    = (const float*)d_in[1];
    const float* Wq_down  = (const float*)d_in[3];
    const float* bq_down  = (const float*)d_in[4];
    const float* q_norm   = (const float*)d_in[5];
    const float* Wq_up    = (const float*)d_in[6];
    const float* bq_up    = (const float*)d_in[7];
    const float* Wkv_down = (const float*)d_in[8];
    const float* bkv_down = (const float*)d_in[9];
    const float* kv_norm  = (const float*)d_in[10];
    const float* Wkv_up   = (const float*)d_in[11];
    const float* bkv_up   = (const float*)d_in[12];
    const float* Wo       = (const float*)d_in[13];
    const float* bo       = (const float*)d_in[14];
    float* out = (float*)d_out;

    void* p;
    #define SYM(var, sym, T) cudaGetSymbolAddress(&p, sym); T* var = (T*)p
    SYM(qmid,  g_qmid,  float);  SYM(kvd,   g_kvd,   float);
    SYM(xh,  g_xh,  bf16); SYM(xl,  g_xl,  bf16);
    SYM(qlh, g_qlh, bf16); SYM(qll, g_qll, bf16);
    SYM(klh, g_klh, bf16); SYM(kll, g_kll, bf16);
    SYM(Qzh, g_Qzh, bf16); SYM(Qzl, g_Qzl, bf16);
    SYM(Kfh, g_Kfh, bf16); SYM(Kfl, g_Kfl, bf16);
    SYM(Vzh, g_Vzh, bf16); SYM(Vzl, g_Vzl, bf16);
    SYM(Oh,  g_Oh,  bf16); SYM(Ol,  g_Ol,  bf16);
    SYM(Wqdh, g_Wqdh, bf16); SYM(Wqdl, g_Wqdl, bf16);
    SYM(Wquh, g_Wquh, bf16); SYM(Wqul, g_Wqul, bf16);
    SYM(Wkdh, g_Wkdh, bf16); SYM(Wkdl, g_Wkdl, bf16);
    SYM(Wkuh, g_Wkuh, bf16); SYM(Wkul, g_Wkul, bf16);
    SYM(Woh,  g_Woh,  bf16); SYM(Wol,  g_Wol,  bf16);
    #undef SYM

    const float scale = 1.0f / sqrtf((float)QK_);
    const int FLASH_SMEM = (2 * 128 * QP + 2 * 64 * QP + 4 * 64 * VP) * 2;  // 223232 B
    cudaFuncSetAttribute(flash_kernel, cudaFuncAttributeMaxDynamicSharedMemorySize, FLASH_SMEM);

    // 0) all fp32->bf16 hi/lo splits in one launch (wide 16B stores)
    SplitJobs SJ;
    SJ.src[0] = x;        SJ.hi[0] = xh;   SJ.lo[0] = xl;
    SJ.src[1] = Wq_down;  SJ.hi[1] = Wqdh; SJ.lo[1] = Wqdl;
    SJ.src[2] = Wq_up;    SJ.hi[2] = Wquh; SJ.lo[2] = Wqul;
    SJ.src[3] = Wkv_down; SJ.hi[3] = Wkdh; SJ.lo[3] = Wkdl;
    SJ.src[4] = Wkv_up;   SJ.hi[4] = Wkuh; SJ.lo[4] = Wkul;
    SJ.src[5] = Wo;       SJ.hi[5] = Woh;  SJ.lo[5] = Wol;
    long long n4s[6] = {
        (long long)M_ROWS*DIM_/4, (long long)QL*DIM_/4, (long long)NQK*QL/4,
        (long long)KVD_*DIM_/4,   (long long)NKV*KVL/4, (long long)DIM_*DIM_/4 };
    SJ.off[0] = 0;
    for (int i = 0; i < 6; i++) SJ.off[i+1] = SJ.off[i] + n4s[i];
    long long ngroups = SJ.off[6] / 2;
    split_multi_kernel<<<(int)((ngroups + 255) / 256), 256>>>(SJ);

    auto mkjob = [](const bf16* Ah, const bf16* Al, const bf16* Bh, const bf16* Bl,
                    const float* bias, float* C,
                    bf16* P1h, bf16* P1l, bf16* P2h, bf16* P2l,
                    int N, int K, int lda, int ldb, int ldc, int epi, int tile_off) {
        GemmJob j;
        j.Ah = Ah; j.Al = Al; j.Bh = Bh; j.Bl = Bl; j.bias = bias; j.C = C;
        j.P1h = P1h; j.P1l = P1l; j.P2h = P2h; j.P2l = P2l;
        j.N = N; j.K = K; j.lda = lda; j.ldb = ldb; j.ldc = ldc;
        j.ntx = (N + 127) / 128; j.epi = epi; j.tile_off = tile_off;
        return j;
    };

    // 1) merged down-projections: q_mid (384 tiles) + kvd (160 tiles)
    {
        GemmJobs JB;
        JB.njobs = 2; JB.freqs = freqs; JB.scale = scale;
        JB.j[0] = mkjob(xh, xl, Wqdh, Wqdl, bq_down, qmid,
                        nullptr, nullptr, nullptr, nullptr,
                        QL, DIM_, DIM_, DIM_, QL, 0, 0);
        int t0 = (QL/128) * (M_ROWS/128);
        JB.j[1] = mkjob(xh, xl, Wkdh, Wkdl, bkv_down, kvd,
                        nullptr, nullptr, nullptr, nullptr,
                        KVD_, DIM_, DIM_, DIM_, KVD_, 0, t0);
        int total = t0 + ((KVD_+127)/128) * (M_ROWS/128);
        mma_gemm_multi<<<total, 256>>>(JB);
    }
    // 2) merged rmsnorm
    rmsnorm2_kernel<<<2 * M_ROWS, 256>>>(qmid, q_norm, qlh, qll,
                                         kvd, kv_norm, klh, kll);
    // 3) K rope -> Kf cols 128..191
    k_rope_kernel<<<(M_ROWS*(ROPE_D/2) + 255)/256, 256>>>(kvd, freqs, Kfh, Kfl);
    // 4) merged up-projections: Q (768 tiles, EPI1) + KV (1024 tiles, EPI2)
    {
        GemmJobs JB;
        JB.njobs = 2; JB.freqs = freqs; JB.scale = scale;
        JB.j[0] = mkjob(qlh, qll, Wquh, Wqul, bq_up, nullptr,
                        Qzh, Qzl, nullptr, nullptr,
                        NQK, QL, QL, QL, NQK, 1, 0);
        int t0 = (NQK/128) * (M_ROWS/128);
        JB.j[1] = mkjob(klh, kll, Wkuh, Wkul, bkv_up, nullptr,
                        Kfh, Kfl, Vzh, Vzl,
                        NKV, KVL, KVL, KVL, NKV, 2, t0);
        int total = t0 + (NKV/128) * (M_ROWS/128);
        mma_gemm_multi<<<total, 256>>>(JB);
    }
    // 5) pipelined flash attention -> Oh/Ol
    flash_kernel<<<dim3(16, BATCH*NH_), 256, FLASH_SMEM>>>(
        Qzh, Qzl, Kfh, Kfl, Vzh, Vzl, Oh, Ol);
    // 6) out = O @ Wo^T + b
    {
        GemmJobs JB;
        JB.njobs = 1; JB.freqs = freqs; JB.scale = scale;
        JB.j[0] = mkjob(Oh, Ol, Woh, Wol, bo, out,
                        nullptr, nullptr, nullptr, nullptr,
                        DIM_, NH_*VDIM_, NH_*VDIM_, NH_*VDIM_, DIM_, 0, 0);
        mma_gemm_multi<<<(DIM_/128) * (M_ROWS/128), 256>>>(JB);
    }
}

// round 16
// speedup vs baseline: 1.3900x; 1.3777x over previous
#include <cuda_runtime.h>
#include <cuda_fp16.h>
#include <math.h>
#include <stdint.h>

typedef __half f16;

// ---------------- problem constants ----------------
#define S_LEN   2048
#define BATCH   2
#define M_ROWS  4096
#define DIM_    2048
#define QL      1536
#define NH_     16
#define QK_     192
#define NOPE_   128
#define ROPE_D  64
#define VDIM_   128
#define KVL     512
#define KVD_    576
#define NQK     (NH_*QK_)            // 3072
#define NKV     (NH_*(NOPE_+VDIM_))  // 4096
#define EPS_    1.1920929e-07f
#define PITCH   24                   // gemm smem pitch (f16)
#define QP      200                  // flash Q/K smem pitch (f16)
#define VP      136                  // flash V smem pitch (f16)

// ---------------- scratch ----------------
__device__ float g_qmid [(size_t)M_ROWS * QL];
__device__ float g_kvd  [(size_t)M_ROWS * KVD_];

// A-side operands: single fp16
__device__ f16 g_xh [(size_t)M_ROWS*DIM_];
__device__ f16 g_qlh[(size_t)M_ROWS*QL];
__device__ f16 g_klh[(size_t)M_ROWS*KVL];
__device__ f16 g_Qzh[(size_t)BATCH*NH_*S_LEN*QK_];
__device__ f16 g_Oh [(size_t)M_ROWS*DIM_];
// B-side operands: fp16 hi/lo pairs
__device__ f16 g_Kfh[(size_t)BATCH*NH_*S_LEN*QK_],  g_Kfl[(size_t)BATCH*NH_*S_LEN*QK_];
__device__ f16 g_Vzh[(size_t)BATCH*NH_*S_LEN*VDIM_],g_Vzl[(size_t)BATCH*NH_*S_LEN*VDIM_];
__device__ f16 g_Wqdh[(size_t)QL*DIM_],   g_Wqdl[(size_t)QL*DIM_];
__device__ f16 g_Wquh[(size_t)NQK*QL],    g_Wqul[(size_t)NQK*QL];
__device__ f16 g_Wkdh[(size_t)KVD_*DIM_], g_Wkdl[(size_t)KVD_*DIM_];
__device__ f16 g_Wkuh[(size_t)NKV*KVL],   g_Wkul[(size_t)NKV*KVL];
__device__ f16 g_Woh [(size_t)DIM_*DIM_], g_Wol [(size_t)DIM_*DIM_];

// ---------------- PTX helpers ----------------
__device__ __forceinline__ uint32_t smem_u32(const void* p) {
    uint32_t a;
    asm("{ .reg .u64 t; cvta.to.shared.u64 t, %1; cvt.u32.u64 %0, t; }"
        : "=r"(a) : "l"(p));
    return a;
}
__device__ __forceinline__ void cp_async16(uint32_t saddr, const void* g, int sz) {
    asm volatile("cp.async.cg.shared.global [%0], [%1], 16, %2;\n"
                 :: "r"(saddr), "l"(g), "r"(sz));
}
__device__ __forceinline__ void cp_commit() { asm volatile("cp.async.commit_group;\n"); }
template<int N> __device__ __forceinline__ void cp_wait() {
    asm volatile("cp.async.wait_group %0;\n" :: "n"(N));
}
__device__ __forceinline__ void ldsm4(uint32_t a[4], uint32_t addr) {
    asm volatile("ldmatrix.sync.aligned.m8n8.x4.shared.b16 {%0,%1,%2,%3}, [%4];\n"
                 : "=r"(a[0]), "=r"(a[1]), "=r"(a[2]), "=r"(a[3]) : "r"(addr));
}
__device__ __forceinline__ void ldsm4t(uint32_t a[4], uint32_t addr) {
    asm volatile("ldmatrix.sync.aligned.m8n8.x4.trans.shared.b16 {%0,%1,%2,%3}, [%4];\n"
                 : "=r"(a[0]), "=r"(a[1]), "=r"(a[2]), "=r"(a[3]) : "r"(addr));
}
__device__ __forceinline__ void ldsm2(uint32_t b[2], uint32_t addr) {
    asm volatile("ldmatrix.sync.aligned.m8n8.x2.shared.b16 {%0,%1}, [%2];\n"
                 : "=r"(b[0]), "=r"(b[1]) : "r"(addr));
}
__device__ __forceinline__ void mma16816(float c[4], const uint32_t a[4], const uint32_t b[2]) {
    asm volatile(
        "mma.sync.aligned.m16n8k16.row.col.f32.f16.f16.f32 "
        "{%0,%1,%2,%3}, {%4,%5,%6,%7}, {%8,%9}, {%0,%1,%2,%3};\n"
        : "+f"(c[0]), "+f"(c[1]), "+f"(c[2]), "+f"(c[3])
        : "r"(a[0]), "r"(a[1]), "r"(a[2]), "r"(a[3]), "r"(b[0]), "r"(b[1]));
}
__device__ __forceinline__ uint32_t pack2h(float a, float b) {
    __half2 t = __floats2half2_rn(a, b);
    return *reinterpret_cast<uint32_t*>(&t);
}
__device__ __forceinline__ void split1h(float v, f16& h, f16& l) {
    h = __float2half_rn(v);
    l = __float2half_rn(v - __half2float(h));
}
__device__ __forceinline__ void split2h(float a, float b, uint32_t& h, uint32_t& l) {
    __half2 hh = __floats2half2_rn(a, b);
    float ra = a - __half2float(__low2half(hh));
    float rb = b - __half2float(__high2half(hh));
    __half2 ll = __floats2half2_rn(ra, rb);
    h = *reinterpret_cast<uint32_t*>(&hh);
    l = *reinterpret_cast<uint32_t*>(&ll);
}

// ---------------- multi-job 2-term fp16 GEMM ----------------
// C[M,N] = Ah[M,K](fp16) * (Bh+Bl)[N,K]^T + bias   (2 MMAs per fragment pair)
// epi 0: fp32 C.  epi 1: Q rope+scale -> single-fp16 P1h [z][s][192].
// epi 2: KV unpack -> Kf hi/lo (P1) + Vz hi/lo (P2).
struct GemmJob {
    const f16 *Ah, *Bh, *Bl;
    const float* bias;
    float* C;
    f16 *P1h, *P1l, *P2h, *P2l;
    int N, K, lda, ldb, ldc;
    int ntx;
    int epi;
    int tile_off;
};
struct GemmJobs {
    GemmJob j[2];
    int njobs;
    const float* freqs;
    float scale;
};

__global__ void __launch_bounds__(256, 2)
mma_gemm_multi(GemmJobs JB)
{
    __shared__ f16 sm[2][3][128][PITCH];   // [stage][Ah,Bh,Bl][row][col] 36864 B

    int bid = blockIdx.x;
    const int jidx = (JB.njobs > 1 && bid >= JB.j[1].tile_off) ? 1 : 0;
    const GemmJob& J = JB.j[jidx];
    bid -= J.tile_off;

    const int m0 = (bid / J.ntx) * 128, n0 = (bid % J.ntx) * 128;
    const int N = J.N, K = J.K, lda = J.lda, ldb = J.ldb;
    const int nk = K >> 4;
    const int tid = threadIdx.x, lane = tid & 31, warp = tid >> 5;
    const int wm = (warp >> 2) * 64, wn = (warp & 3) * 32;
    const int lr = tid >> 1, seg = tid & 1;
    const uint32_t smbase = (uint32_t)__cvta_generic_to_shared(&sm[0][0][0][0]);

    float acc[4][4][4];
    #pragma unroll
    for (int i = 0; i < 4; i++)
        #pragma unroll
        for (int j = 0; j < 4; j++)
            #pragma unroll
            for (int r = 0; r < 4; r++) acc[i][j][r] = 0.f;

    auto issue = [&](int st, int k0) {
        const f16* ga = J.Ah + (size_t)(m0 + lr) * lda + k0 + seg * 8;
        cp_async16(smbase + ((((st*3+0)*128 + lr)*PITCH + seg*8) << 1), ga, 16);
        int rr = n0 + lr;
        int sz = (rr < N) ? 16 : 0;
        int rc = (rr < N) ? rr : 0;
        const f16* gb0 = J.Bh + (size_t)rc * ldb + k0 + seg * 8;
        const f16* gb1 = J.Bl + (size_t)rc * ldb + k0 + seg * 8;
        cp_async16(smbase + ((((st*3+1)*128 + lr)*PITCH + seg*8) << 1), gb0, sz);
        cp_async16(smbase + ((((st*3+2)*128 + lr)*PITCH + seg*8) << 1), gb1, sz);
    };

    auto compute = [&](int st) {
        uint32_t af[4][4], bfr[4][2][2];
        #pragma unroll
        for (int mi = 0; mi < 4; mi++) {
            int row = wm + mi * 16 + (lane & 15);
            uint32_t ad = smbase + ((((st*3+0)*128 + row)*PITCH + (lane >> 4)*8) << 1);
            ldsm4(af[mi], ad);
        }
        #pragma unroll
        for (int ni = 0; ni < 4; ni++)
            #pragma unroll
            for (int p = 0; p < 2; p++) {
                int row = wn + ni * 8 + (lane & 7);
                uint32_t ad = smbase + ((((st*3+1+p)*128 + row)*PITCH + ((lane & 8) ? 8 : 0)) << 1);
                ldsm2(bfr[ni][p], ad);
            }
        #pragma unroll
        for (int mi = 0; mi < 4; mi++)
            #pragma unroll
            for (int ni = 0; ni < 4; ni++) {
                mma16816(acc[mi][ni], af[mi], bfr[ni][0]);   // Ah*Bh
                mma16816(acc[mi][ni], af[mi], bfr[ni][1]);   // Ah*Bl
            }
    };

    issue(0, 0); cp_commit();
    for (int i = 0; i < nk; i++) {
        int cur = i & 1;
        if (i + 1 < nk) { issue(cur ^ 1, (i + 1) << 4); cp_commit(); cp_wait<1>(); }
        else            { cp_wait<0>(); }
        __syncthreads();
        compute(cur);
        __syncthreads();
    }

    const int g = lane >> 2, tg = lane & 3;
    const int epi = J.epi;
    #pragma unroll
    for (int mi = 0; mi < 4; mi++) {
        const int rbase = m0 + wm + mi * 16 + g;
        #pragma unroll
        for (int ni = 0; ni < 4; ni++) {
            int c0 = n0 + wn + ni * 8 + 2 * tg;
            float bv0 = 0.f, bv1 = 0.f;
            if (J.bias) {
                if (c0 < N)     bv0 = J.bias[c0];
                if (c0 + 1 < N) bv1 = J.bias[c0 + 1];
            }
            #pragma unroll
            for (int half = 0; half < 2; half++) {
                const int r = rbase + half * 8;
                float v0 = acc[mi][ni][half * 2]     + bv0;
                float v1 = acc[mi][ni][half * 2 + 1] + bv1;
                if (epi == 0) {
                    long long rr = r;
                    if (c0 < N)     J.C[rr * J.ldc + c0]     = v0;
                    if (c0 + 1 < N) J.C[rr * J.ldc + c0 + 1] = v1;
                } else {
                    const int s = r & (S_LEN - 1), zb = r >> 11;
                    if (epi == 1) {
                        int h = c0 / QK_, d = c0 % QK_;
                        float y0 = v0, y1 = v1;
                        if (d >= NOPE_) {
                            int dp = (d - NOPE_) >> 1;
                            float f = JB.freqs[s * (ROPE_D / 2) + dp];
                            float cc = cosf(f), ss = sinf(f);
                            y0 = v0 * cc - v1 * ss;
                            y1 = v0 * ss + v1 * cc;
                        }
                        y0 *= JB.scale; y1 *= JB.scale;
                        size_t o = ((size_t)(zb * NH_ + h) * S_LEN + s) * QK_ + d;
                        *reinterpret_cast<uint32_t*>(J.P1h + o) = pack2h(y0, y1);
                    } else {
                        int h = c0 >> 8, d = c0 & 255;
                        uint32_t hh, ll;
                        split2h(v0, v1, hh, ll);
                        if (d < NOPE_) {
                            size_t o = ((size_t)(zb * NH_ + h) * S_LEN + s) * QK_ + d;
                            *reinterpret_cast<uint32_t*>(J.P1h + o) = hh;
                            *reinterpret_cast<uint32_t*>(J.P1l + o) = ll;
                        } else {
                            size_t o = ((size_t)(zb * NH_ + h) * S_LEN + s) * VDIM_ + (d - NOPE_);
                            *reinterpret_cast<uint32_t*>(J.P2h + o) = hh;
                            *reinterpret_cast<uint32_t*>(J.P2l + o) = ll;
                        }
                    }
                }
            }
        }
    }
}

// ---------------- fused flash attention (fp16 2-term; Q single) ----------
__global__ void __launch_bounds__(256, 1)
flash_kernel(const f16* __restrict__ Qh,
             const f16* __restrict__ Kh, const f16* __restrict__ Kl,
             const f16* __restrict__ Vh, const f16* __restrict__ Vl,
             f16* __restrict__ Oh)
{
    extern __shared__ f16 fs[];
    f16* Qhs = fs;                       // 128 x QP
    f16* Khs = Qhs + 128 * QP;           // 64 x QP
    f16* Kls = Khs + 64 * QP;            // 64 x QP
    f16* Vst = Kls + 64 * QP;            // Vh0, Vl0, Vh1, Vl1 (64 x VP each)

    const int z = blockIdx.y, zb = z >> 4, zh = z & 15;
    const int mt = (int)gridDim.x - 1 - (int)blockIdx.x;
    const int m0 = mt * 128;
    const int tid = threadIdx.x, lane = tid & 31, warp = tid >> 5;
    const int g = lane >> 2, tg = lane & 3;
    const int wr = warp * 16;

    const uint32_t sQh = smem_u32(Qhs);
    const uint32_t sKh = smem_u32(Khs), sKl = smem_u32(Kls);
    const uint32_t sV0 = smem_u32(Vst);
    const uint32_t VSTRIDE = 64 * VP * 2;

    const size_t qzb = (size_t)z * S_LEN * QK_;
    const size_t vzb = (size_t)z * S_LEN * VDIM_;

    auto issue_K = [&](int k0) {
        for (int i = tid; i < 64 * 24; i += 256) {
            int r = i / 24, c = (i % 24) * 8;
            size_t go = qzb + (size_t)(k0 + r) * QK_ + c;
            uint32_t so = (uint32_t)((r * QP + c) * 2);
            cp_async16(sKh + so, Kh + go, 16);
            cp_async16(sKl + so, Kl + go, 16);
        }
    };
    auto issue_V = [&](int k0, int stage) {
        uint32_t base = sV0 + (uint32_t)stage * 2 * VSTRIDE;
        for (int i = tid; i < 64 * 16; i += 256) {
            int r = i / 16, c = (i % 16) * 8;
            size_t go = vzb + (size_t)(k0 + r) * VDIM_ + c;
            uint32_t so = (uint32_t)((r * VP + c) * 2);
            cp_async16(base + so, Vh + go, 16);
            cp_async16(base + VSTRIDE + so, Vl + go, 16);
        }
    };

    for (int i = tid; i < 128 * 24; i += 256) {
        int r = i / 24, c = (i % 24) * 8;
        size_t go = qzb + (size_t)(m0 + r) * QK_ + c;
        uint32_t so = (uint32_t)((r * QP + c) * 2);
        cp_async16(sQh + so, Qh + go, 16);
    }
    cp_commit();
    issue_K(0);  cp_commit();
    issue_V(0, 0); cp_commit();

    float mr0 = -1e30f, mr1 = -1e30f, lr0 = 0.f, lr1 = 0.f;
    float oacc[16][4];
    #pragma unroll
    for (int i = 0; i < 16; i++)
        #pragma unroll
        for (int j = 0; j < 4; j++) oacc[i][j] = 0.f;

    const int nkt = (m0 + 128) / 64;
    for (int kt = 0; kt < nkt; kt++) {
        const int k0 = kt * 64;
        const int cur = kt & 1;

        __syncthreads();                      // sync1: PV readers of stage cur^1 done
        if (kt + 1 < nkt) issue_V((kt + 1) * 64, cur ^ 1);
        cp_commit();
        if (kt + 1 < nkt) cp_wait<1>();
        else             cp_wait<0>();
        __syncthreads();                      // sync2

        float sacc[8][4];
        #pragma unroll
        for (int i = 0; i < 8; i++)
            #pragma unroll
            for (int j = 0; j < 4; j++) sacc[i][j] = 0.f;

        #pragma unroll
        for (int ks = 0; ks < 12; ks++) {
            uint32_t ah[4];
            uint32_t aoff = (uint32_t)(((wr + (lane & 15)) * QP + ks * 16 + (lane >> 4) * 8) * 2);
            ldsm4(ah, sQh + aoff);
            #pragma unroll
            for (int np = 0; np < 4; np++) {
                uint32_t kh4[4], kl4[4];
                uint32_t boff = (uint32_t)(((np * 16 + (lane & 15)) * QP + ks * 16 + (lane >> 4) * 8) * 2);
                ldsm4(kh4, sKh + boff);
                ldsm4(kl4, sKl + boff);
                uint32_t b0h[2] = {kh4[0], kh4[2]}, b1h[2] = {kh4[1], kh4[3]};
                uint32_t b0l[2] = {kl4[0], kl4[2]}, b1l[2] = {kl4[1], kl4[3]};
                mma16816(sacc[2*np],   ah, b0h);
                mma16816(sacc[2*np],   ah, b0l);
                mma16816(sacc[2*np+1], ah, b1h);
                mma16816(sacc[2*np+1], ah, b1l);
            }
        }

        __syncthreads();                      // sync3: K readers done
        if (kt + 1 < nkt) issue_K((kt + 1) * 64);
        cp_commit();

        if (k0 + 63 > m0) {
            int r0 = m0 + wr + g, r1 = r0 + 8;
            #pragma unroll
            for (int ni = 0; ni < 8; ni++) {
                int c0 = k0 + ni * 8 + 2 * tg;
                if (c0     > r0) sacc[ni][0] = -1e30f;
                if (c0 + 1 > r0) sacc[ni][1] = -1e30f;
                if (c0     > r1) sacc[ni][2] = -1e30f;
                if (c0 + 1 > r1) sacc[ni][3] = -1e30f;
            }
        }

        float mx0 = -1e30f, mx1 = -1e30f;
        #pragma unroll
        for (int ni = 0; ni < 8; ni++) {
            mx0 = fmaxf(mx0, fmaxf(sacc[ni][0], sacc[ni][1]));
            mx1 = fmaxf(mx1, fmaxf(sacc[ni][2], sacc[ni][3]));
        }
        mx0 = fmaxf(mx0, __shfl_xor_sync(0xffffffffu, mx0, 1));
        mx0 = fmaxf(mx0, __shfl_xor_sync(0xffffffffu, mx0, 2));
        mx1 = fmaxf(mx1, __shfl_xor_sync(0xffffffffu, mx1, 1));
        mx1 = fmaxf(mx1, __shfl_xor_sync(0xffffffffu, mx1, 2));
        float nm0 = fmaxf(mr0, mx0), nm1 = fmaxf(mr1, mx1);
        float al0 = __expf(mr0 - nm0), al1 = __expf(mr1 - nm1);
        mr0 = nm0; mr1 = nm1;
        float s0 = 0.f, s1 = 0.f;
        #pragma unroll
        for (int ni = 0; ni < 8; ni++) {
            sacc[ni][0] = __expf(sacc[ni][0] - nm0);
            sacc[ni][1] = __expf(sacc[ni][1] - nm0);
            sacc[ni][2] = __expf(sacc[ni][2] - nm1);
            sacc[ni][3] = __expf(sacc[ni][3] - nm1);
            s0 += sacc[ni][0] + sacc[ni][1];
            s1 += sacc[ni][2] + sacc[ni][3];
        }
        s0 += __shfl_xor_sync(0xffffffffu, s0, 1);
        s0 += __shfl_xor_sync(0xffffffffu, s0, 2);
        s1 += __shfl_xor_sync(0xffffffffu, s1, 1);
        s1 += __shfl_xor_sync(0xffffffffu, s1, 2);
        lr0 = lr0 * al0 + s0;
        lr1 = lr1 * al1 + s1;
        #pragma unroll
        for (int i = 0; i < 16; i++) {
            oacc[i][0] *= al0; oacc[i][1] *= al0;
            oacc[i][2] *= al1; oacc[i][3] *= al1;
        }

        const uint32_t sVh = sV0 + (uint32_t)cur * 2 * VSTRIDE;
        const uint32_t sVl = sVh + VSTRIDE;
        #pragma unroll
        for (int kk = 0; kk < 4; kk++) {
            uint32_t pah[4];
            pah[0] = pack2h(sacc[2*kk][0],   sacc[2*kk][1]);
            pah[1] = pack2h(sacc[2*kk][2],   sacc[2*kk][3]);
            pah[2] = pack2h(sacc[2*kk+1][0], sacc[2*kk+1][1]);
            pah[3] = pack2h(sacc[2*kk+1][2], sacc[2*kk+1][3]);
            #pragma unroll
            for (int np = 0; np < 8; np++) {
                uint32_t vh4[4], vl4[4];
                uint32_t voff = (uint32_t)(((kk * 16 + (lane & 15)) * VP + np * 16 + (lane >> 4) * 8) * 2);
                ldsm4t(vh4, sVh + voff);
                ldsm4t(vl4, sVl + voff);
                uint32_t bh0[2] = {vh4[0], vh4[1]}, bh1[2] = {vh4[2], vh4[3]};
                uint32_t bl0[2] = {vl4[0], vl4[1]}, bl1[2] = {vl4[2], vl4[3]};
                mma16816(oacc[2*np],   pah, bh0);
                mma16816(oacc[2*np],   pah, bl0);
                mma16816(oacc[2*np+1], pah, bh1);
                mma16816(oacc[2*np+1], pah, bl1);
            }
        }
    }

    float i0 = 1.f / lr0, i1 = 1.f / lr1;
    size_t row0 = (size_t)(zb * S_LEN + m0 + wr + g) * DIM_ + zh * VDIM_;
    size_t row1 = row0 + (size_t)8 * DIM_;
    #pragma unroll
    for (int ni = 0; ni < 16; ni++) {
        int d = ni * 8 + 2 * tg;
        *reinterpret_cast<uint32_t*>(Oh + row0 + d) = pack2h(oacc[ni][0] * i0, oacc[ni][1] * i0);
        *reinterpret_cast<uint32_t*>(Oh + row1 + d) = pack2h(oacc[ni][2] * i1, oacc[ni][3] * i1);
    }
}

// ---------------- multi-segment fp32 -> fp16 split (lo optional) ----------
struct SplitJobs {
    const float* src[6];
    f16* hi[6];
    f16* lo[6];          // nullptr => hi-only segment
    long long off[7];    // prefix offsets in float4 units (all even)
};
__global__ void __launch_bounds__(256)
split_multi_kernel(SplitJobs J)
{
    long long gidx = (long long)blockIdx.x * 256 + threadIdx.x;   // 2 float4 per thread
    if (gidx * 2 >= J.off[6]) return;
    long long idx = gidx * 2;
    int j = 0;
    #pragma unroll
    for (int t = 1; t < 6; t++) if (idx >= J.off[t]) j = t;
    long long i = idx - J.off[j];
    float4 v0 = reinterpret_cast<const float4*>(J.src[j])[i];
    float4 v1 = reinterpret_cast<const float4*>(J.src[j])[i + 1];
    float f[8] = {v0.x, v0.y, v0.z, v0.w, v1.x, v1.y, v1.z, v1.w};
    union { f16 b[8]; uint4 u; } H, L;
    #pragma unroll
    for (int k = 0; k < 8; k++) split1h(f[k], H.b[k], L.b[k]);
    reinterpret_cast<uint4*>(J.hi[j])[i >> 1] = H.u;
    if (J.lo[j]) reinterpret_cast<uint4*>(J.lo[j])[i >> 1] = L.u;
}

// ---------------- merged RMSNorm (q rows then kv rows) -> fp16 -------------
__global__ void __launch_bounds__(256)
rmsnorm2_kernel(const float* __restrict__ qin, const float* __restrict__ qw,
                f16* __restrict__ qh,
                const float* __restrict__ kin, const float* __restrict__ kw,
                f16* __restrict__ kh)
{
    long long row = blockIdx.x;
    const float* p; const float* w; f16* oh; int n;
    if (row < M_ROWS) {
        p = qin + row * QL; w = qw; oh = qh + row * QL; n = QL;
    } else {
        row -= M_ROWS;
        p = kin + row * KVD_; w = kw; oh = kh + row * KVL; n = KVL;
    }
    float s = 0.f;
    for (int i = threadIdx.x; i < n; i += 256) { float v = p[i]; s += v * v; }
    __shared__ float red[256];
    red[threadIdx.x] = s; __syncthreads();
    for (int st = 128; st > 0; st >>= 1) {
        if (threadIdx.x < st) red[threadIdx.x] += red[threadIdx.x + st];
        __syncthreads();
    }
    float scale = rsqrtf(red[0] / (float)n + EPS_);
    for (int i = threadIdx.x; i < n; i += 256)
        oh[i] = __float2half_rn(p[i] * scale * w[i]);
}

// ---------------- K rope: rope(kvd cols 512..575) -> Kf cols 128..191 ------
__global__ void __launch_bounds__(256)
k_rope_kernel(const float* __restrict__ kvd, const float* __restrict__ freqs,
              f16* __restrict__ Kfh, f16* __restrict__ Kfl)
{
    int idx = blockIdx.x * 256 + threadIdx.x;
    const int total = M_ROWS * (ROPE_D / 2);
    if (idx >= total) return;
    int dp = idx % (ROPE_D / 2);
    int m  = idx / (ROPE_D / 2);
    int s  = m & (S_LEN - 1);
    int zb = m >> 11;
    float f = freqs[s * (ROPE_D / 2) + dp];
    float c = cosf(f), sn = sinf(f);
    float x0 = kvd[(size_t)m * KVD_ + KVL + 2 * dp];
    float x1 = kvd[(size_t)m * KVD_ + KVL + 2 * dp + 1];
    float y0 = x0 * c - x1 * sn;
    float y1 = x0 * sn + x1 * c;
    uint32_t hh, ll;
    split2h(y0, y1, hh, ll);
    #pragma unroll
    for (int h = 0; h < NH_; h++) {
        size_t o = ((size_t)(zb * NH_ + h) * S_LEN + s) * QK_ + NOPE_ + 2 * dp;
        *reinterpret_cast<uint32_t*>(Kfh + o) = hh;
        *reinterpret_cast<uint32_t*>(Kfl + o) = ll;
    }
}

// ---------------- host ----------------
extern "C" void kernel_launch(void* const* d_in, const int* in_sizes, int n_in,
                              void* d_out, int out_size)
{
    (void)in_sizes; (void)n_in; (void)out_size;
    const float* x        = (const float*)d_in[0];
    const float* freqs    = (const float*)d_in[1];
    const float* Wq_down  = (const float*)d_in[3];
    const float* bq_down  = (const float*)d_in[4];
    const float* q_norm   = (const float*)d_in[5];
    const float* Wq_up    = (const float*)d_in[6];
    const float* bq_up    = (const float*)d_in[7];
    const float* Wkv_down = (const float*)d_in[8];
    const float* bkv_down = (const float*)d_in[9];
    const float* kv_norm  = (const float*)d_in[10];
    const float* Wkv_up   = (const float*)d_in[11];
    const float* bkv_up   = (const float*)d_in[12];
    const float* Wo       = (const float*)d_in[13];
    const float* bo       = (const float*)d_in[14];
    float* out = (float*)d_out;

    void* p;
    #define SYM(var, sym, T) cudaGetSymbolAddress(&p, sym); T* var = (T*)p
    SYM(qmid,  g_qmid,  float);  SYM(kvd,   g_kvd,   float);
    SYM(xh,  g_xh,  f16);
    SYM(qlh, g_qlh, f16); SYM(klh, g_klh, f16);
    SYM(Qzh, g_Qzh, f16);
    SYM(Kfh, g_Kfh, f16); SYM(Kfl, g_Kfl, f16);
    SYM(Vzh, g_Vzh, f16); SYM(Vzl, g_Vzl, f16);
    SYM(Oh,  g_Oh,  f16);
    SYM(Wqdh, g_Wqdh, f16); SYM(Wqdl, g_Wqdl, f16);
    SYM(Wquh, g_Wquh, f16); SYM(Wqul, g_Wqul, f16);
    SYM(Wkdh, g_Wkdh, f16); SYM(Wkdl, g_Wkdl, f16);
    SYM(Wkuh, g_Wkuh, f16); SYM(Wkul, g_Wkul, f16);
    SYM(Woh,  g_Woh,  f16); SYM(Wol,  g_Wol,  f16);
    #undef SYM

    const float scale = 1.0f / sqrtf((float)QK_);
    // Q single + K hi/lo + V double-buffered hi/lo
    const int FLASH_SMEM = (128 * QP + 2 * 64 * QP + 4 * 64 * VP) * 2;  // 172032 B
    cudaFuncSetAttribute(flash_kernel, cudaFuncAttributeMaxDynamicSharedMemorySize, FLASH_SMEM);

    // 0) all fp32->fp16 splits in one launch (x hi-only; weights hi+lo)
    SplitJobs SJ;
    SJ.src[0] = x;        SJ.hi[0] = xh;   SJ.lo[0] = nullptr;
    SJ.src[1] = Wq_down;  SJ.hi[1] = Wqdh; SJ.lo[1] = Wqdl;
    SJ.src[2] = Wq_up;    SJ.hi[2] = Wquh; SJ.lo[2] = Wqul;
    SJ.src[3] = Wkv_down; SJ.hi[3] = Wkdh; SJ.lo[3] = Wkdl;
    SJ.src[4] = Wkv_up;   SJ.hi[4] = Wkuh; SJ.lo[4] = Wkul;
    SJ.src[5] = Wo;       SJ.hi[5] = Woh;  SJ.lo[5] = Wol;
    long long n4s[6] = {
        (long long)M_ROWS*DIM_/4, (long long)QL*DIM_/4, (long long)NQK*QL/4,
        (long long)KVD_*DIM_/4,   (long long)NKV*KVL/4, (long long)DIM_*DIM_/4 };
    SJ.off[0] = 0;
    for (int i = 0; i < 6; i++) SJ.off[i+1] = SJ.off[i] + n4s[i];
    long long ngroups = SJ.off[6] / 2;
    split_multi_kernel<<<(int)((ngroups + 255) / 256), 256>>>(SJ);

    auto mkjob = [](const f16* Ah, const f16* Bh, const f16* Bl,
                    const float* bias, float* C,
                    f16* P1h, f16* P1l, f16* P2h, f16* P2l,
                    int N, int K, int lda, int ldb, int ldc, int epi, int tile_off) {
        GemmJob j;
        j.Ah = Ah; j.Bh = Bh; j.Bl = Bl; j.bias = bias; j.C = C;
        j.P1h = P1h; j.P1l = P1l; j.P2h = P2h; j.P2l = P2l;
        j.N = N; j.K = K; j.lda = lda; j.ldb = ldb; j.ldc = ldc;
        j.ntx = (N + 127) / 128; j.epi = epi; j.tile_off = tile_off;
        return j;
    };

    // 1) merged down-projections: q_mid (384 tiles) + kvd (160 tiles)
    {
        GemmJobs JB;
        JB.njobs = 2; JB.freqs = freqs; JB.scale = scale;
        JB.j[0] = mkjob(xh, Wqdh, Wqdl, bq_down, qmid,
                        nullptr, nullptr, nullptr, nullptr,
                        QL, DIM_, DIM_, DIM_, QL, 0, 0);
        int t0 = (QL/128) * (M_ROWS/128);
        JB.j[1] = mkjob(xh, Wkdh, Wkdl, bkv_down, kvd,
                        nullptr, nullptr, nullptr, nullptr,
                        KVD_, DIM_, DIM_, DIM_, KVD_, 0, t0);
        int total = t0 + ((KVD_+127)/128) * (M_ROWS/128);
        mma_gemm_multi<<<total, 256>>>(JB);
    }
    // 2) merged rmsnorm -> fp16
    rmsnorm2_kernel<<<2 * M_ROWS, 256>>>(qmid, q_norm, qlh, kvd, kv_norm, klh);
    // 3) K rope -> Kf cols 128..191 (hi/lo)
    k_rope_kernel<<<(M_ROWS*(ROPE_D/2) + 255)/256, 256>>>(kvd, freqs, Kfh, Kfl);
    // 4) merged up-projections: Q (768 tiles, EPI1) + KV (1024 tiles, EPI2)
    {
        GemmJobs JB;
        JB.njobs = 2; JB.freqs = freqs; JB.scale = scale;
        JB.j[0] = mkjob(qlh, Wquh, Wqul, bq_up, nullptr,
                        Qzh, nullptr, nullptr, nullptr,
                        NQK, QL, QL, QL, NQK, 1, 0);
        int t0 = (NQK/128) * (M_ROWS/128);
        JB.j[1] = mkjob(klh, Wkuh, Wkul, bkv_up, nullptr,
                        Kfh, Kfl, Vzh, Vzl,
                        NKV, KVL, KVL, KVL, NKV, 2, t0);
        int total = t0 + (NKV/128) * (M_ROWS/128);
        mma_gemm_multi<<<total, 256>>>(JB);
    }
    // 5) pipelined flash attention -> Oh (single fp16)
    flash_kernel<<<dim3(16, BATCH*NH_), 256, FLASH_SMEM>>>(
        Qzh, Kfh, Kfl, Vzh, Vzl, Oh);
    // 6) out = O @ Wo^T + b
    {
        GemmJobs JB;
        JB.njobs = 1; JB.freqs = freqs; JB.scale = scale;
        JB.j[0] = mkjob(Oh, Woh, Wol, bo, out,
                        nullptr, nullptr, nullptr, nullptr,
                        DIM_, NH_*VDIM_, NH_*VDIM_, NH_*VDIM_, DIM_, 0, 0);
        mma_gemm_multi<<<(DIM_/128) * (M_ROWS/128), 256>>>(JB);
    }
}

// round 17
// speedup vs baseline: 2.1366x; 1.5372x over previous
#include <cuda_runtime.h>
#include <cuda_fp16.h>
#include <math.h>
#include <stdint.h>

typedef __half f16;

// ---------------- problem constants ----------------
#define S_LEN   2048
#define BATCH   2
#define M_ROWS  4096
#define DIM_    2048
#define QL      1536
#define NH_     16
#define QK_     192
#define NOPE_   128
#define ROPE_D  64
#define VDIM_   128
#define KVL     512
#define KVD_    576
#define NQK     (NH_*QK_)            // 3072
#define NKV     (NH_*(NOPE_+VDIM_))  // 4096
#define EPS_    1.1920929e-07f
#define PITCH   24                   // gemm smem pitch (f16)
#define QP      200                  // flash Q/K smem pitch (f16)
#define VP      136                  // flash V smem pitch (f16)

// ---------------- scratch ----------------
__device__ float g_qmid [(size_t)M_ROWS * QL];
__device__ float g_kvd  [(size_t)M_ROWS * KVD_];

__device__ f16 g_xh [(size_t)M_ROWS*DIM_];
__device__ f16 g_qlh[(size_t)M_ROWS*QL];
__device__ f16 g_klh[(size_t)M_ROWS*KVL];
__device__ f16 g_Qzh[(size_t)BATCH*NH_*S_LEN*QK_];
__device__ f16 g_Oh [(size_t)M_ROWS*DIM_];
__device__ f16 g_Kfh[(size_t)BATCH*NH_*S_LEN*QK_];
__device__ f16 g_Vzh[(size_t)BATCH*NH_*S_LEN*VDIM_];
__device__ f16 g_Wqdh[(size_t)QL*DIM_];
__device__ f16 g_Wquh[(size_t)NQK*QL];
__device__ f16 g_Wkdh[(size_t)KVD_*DIM_];
__device__ f16 g_Wkuh[(size_t)NKV*KVL];
__device__ f16 g_Woh [(size_t)DIM_*DIM_];

// ---------------- PTX helpers ----------------
__device__ __forceinline__ uint32_t smem_u32(const void* p) {
    uint32_t a;
    asm("{ .reg .u64 t; cvta.to.shared.u64 t, %1; cvt.u32.u64 %0, t; }"
        : "=r"(a) : "l"(p));
    return a;
}
__device__ __forceinline__ void cp_async16(uint32_t saddr, const void* g, int sz) {
    asm volatile("cp.async.cg.shared.global [%0], [%1], 16, %2;\n"
                 :: "r"(saddr), "l"(g), "r"(sz));
}
__device__ __forceinline__ void cp_commit() { asm volatile("cp.async.commit_group;\n"); }
template<int N> __device__ __forceinline__ void cp_wait() {
    asm volatile("cp.async.wait_group %0;\n" :: "n"(N));
}
__device__ __forceinline__ void ldsm4(uint32_t a[4], uint32_t addr) {
    asm volatile("ldmatrix.sync.aligned.m8n8.x4.shared.b16 {%0,%1,%2,%3}, [%4];\n"
                 : "=r"(a[0]), "=r"(a[1]), "=r"(a[2]), "=r"(a[3]) : "r"(addr));
}
__device__ __forceinline__ void ldsm4t(uint32_t a[4], uint32_t addr) {
    asm volatile("ldmatrix.sync.aligned.m8n8.x4.trans.shared.b16 {%0,%1,%2,%3}, [%4];\n"
                 : "=r"(a[0]), "=r"(a[1]), "=r"(a[2]), "=r"(a[3]) : "r"(addr));
}
__device__ __forceinline__ void ldsm2(uint32_t b[2], uint32_t addr) {
    asm volatile("ldmatrix.sync.aligned.m8n8.x2.shared.b16 {%0,%1}, [%2];\n"
                 : "=r"(b[0]), "=r"(b[1]) : "r"(addr));
}
__device__ __forceinline__ void mma16816(float c[4], const uint32_t a[4], const uint32_t b[2]) {
    asm volatile(
        "mma.sync.aligned.m16n8k16.row.col.f32.f16.f16.f32 "
        "{%0,%1,%2,%3}, {%4,%5,%6,%7}, {%8,%9}, {%0,%1,%2,%3};\n"
        : "+f"(c[0]), "+f"(c[1]), "+f"(c[2]), "+f"(c[3])
        : "r"(a[0]), "r"(a[1]), "r"(a[2]), "r"(a[3]), "r"(b[0]), "r"(b[1]));
}
__device__ __forceinline__ uint32_t pack2h(float a, float b) {
    __half2 t = __floats2half2_rn(a, b);
    return *reinterpret_cast<uint32_t*>(&t);
}

// ---------------- multi-job fp16 GEMM (1 MMA per fragment pair) ------------
// C[M,N] = Ah[M,K] * Bh[N,K]^T + bias
// epi 0: fp32 C.  epi 1: Q rope+scale -> fp16 P1h [z][s][192].
// epi 2: KV unpack -> Kf (P1) + Vz (P2), single fp16.
struct GemmJob {
    const f16 *Ah, *Bh;
    const float* bias;
    float* C;
    f16 *P1h, *P2h;
    int N, K, lda, ldb, ldc;
    int ntx;
    int epi;
    int tile_off;
};
struct GemmJobs {
    GemmJob j[2];
    int njobs;
    const float* freqs;
    float scale;
};

__global__ void __launch_bounds__(256, 2)
mma_gemm_multi(GemmJobs JB)
{
    __shared__ f16 sm[2][2][128][PITCH];   // [stage][Ah,Bh][row][col] 24576 B

    int bid = blockIdx.x;
    const int jidx = (JB.njobs > 1 && bid >= JB.j[1].tile_off) ? 1 : 0;
    const GemmJob& J = JB.j[jidx];
    bid -= J.tile_off;

    const int m0 = (bid / J.ntx) * 128, n0 = (bid % J.ntx) * 128;
    const int N = J.N, K = J.K, lda = J.lda, ldb = J.ldb;
    const int nk = K >> 4;
    const int tid = threadIdx.x, lane = tid & 31, warp = tid >> 5;
    const int wm = (warp >> 2) * 64, wn = (warp & 3) * 32;
    const int lr = tid >> 1, seg = tid & 1;
    const uint32_t smbase = (uint32_t)__cvta_generic_to_shared(&sm[0][0][0][0]);

    float acc[4][4][4];
    #pragma unroll
    for (int i = 0; i < 4; i++)
        #pragma unroll
        for (int j = 0; j < 4; j++)
            #pragma unroll
            for (int r = 0; r < 4; r++) acc[i][j][r] = 0.f;

    auto issue = [&](int st, int k0) {
        const f16* ga = J.Ah + (size_t)(m0 + lr) * lda + k0 + seg * 8;
        cp_async16(smbase + ((((st*2+0)*128 + lr)*PITCH + seg*8) << 1), ga, 16);
        int rr = n0 + lr;
        int sz = (rr < N) ? 16 : 0;
        int rc = (rr < N) ? rr : 0;
        const f16* gb = J.Bh + (size_t)rc * ldb + k0 + seg * 8;
        cp_async16(smbase + ((((st*2+1)*128 + lr)*PITCH + seg*8) << 1), gb, sz);
    };

    auto compute = [&](int st) {
        uint32_t af[4][4], bfr[4][2];
        #pragma unroll
        for (int mi = 0; mi < 4; mi++) {
            int row = wm + mi * 16 + (lane & 15);
            uint32_t ad = smbase + ((((st*2+0)*128 + row)*PITCH + (lane >> 4)*8) << 1);
            ldsm4(af[mi], ad);
        }
        #pragma unroll
        for (int ni = 0; ni < 4; ni++) {
            int row = wn + ni * 8 + (lane & 7);
            uint32_t ad = smbase + ((((st*2+1)*128 + row)*PITCH + ((lane & 8) ? 8 : 0)) << 1);
            ldsm2(bfr[ni], ad);
        }
        #pragma unroll
        for (int mi = 0; mi < 4; mi++)
            #pragma unroll
            for (int ni = 0; ni < 4; ni++)
                mma16816(acc[mi][ni], af[mi], bfr[ni]);
    };

    issue(0, 0); cp_commit();
    for (int i = 0; i < nk; i++) {
        int cur = i & 1;
        if (i + 1 < nk) { issue(cur ^ 1, (i + 1) << 4); cp_commit(); cp_wait<1>(); }
        else            { cp_wait<0>(); }
        __syncthreads();
        compute(cur);
        __syncthreads();
    }

    const int g = lane >> 2, tg = lane & 3;
    const int epi = J.epi;
    #pragma unroll
    for (int mi = 0; mi < 4; mi++) {
        const int rbase = m0 + wm + mi * 16 + g;
        #pragma unroll
        for (int ni = 0; ni < 4; ni++) {
            int c0 = n0 + wn + ni * 8 + 2 * tg;
            float bv0 = 0.f, bv1 = 0.f;
            if (J.bias) {
                if (c0 < N)     bv0 = J.bias[c0];
                if (c0 + 1 < N) bv1 = J.bias[c0 + 1];
            }
            #pragma unroll
            for (int half = 0; half < 2; half++) {
                const int r = rbase + half * 8;
                float v0 = acc[mi][ni][half * 2]     + bv0;
                float v1 = acc[mi][ni][half * 2 + 1] + bv1;
                if (epi == 0) {
                    long long rr = r;
                    if (c0 < N)     J.C[rr * J.ldc + c0]     = v0;
                    if (c0 + 1 < N) J.C[rr * J.ldc + c0 + 1] = v1;
                } else {
                    const int s = r & (S_LEN - 1), zb = r >> 11;
                    if (epi == 1) {
                        int h = c0 / QK_, d = c0 % QK_;
                        float y0 = v0, y1 = v1;
                        if (d >= NOPE_) {
                            int dp = (d - NOPE_) >> 1;
                            float f = JB.freqs[s * (ROPE_D / 2) + dp];
                            float cc = cosf(f), ss = sinf(f);
                            y0 = v0 * cc - v1 * ss;
                            y1 = v0 * ss + v1 * cc;
                        }
                        y0 *= JB.scale; y1 *= JB.scale;
                        size_t o = ((size_t)(zb * NH_ + h) * S_LEN + s) * QK_ + d;
                        *reinterpret_cast<uint32_t*>(J.P1h + o) = pack2h(y0, y1);
                    } else {
                        int h = c0 >> 8, d = c0 & 255;
                        uint32_t hh = pack2h(v0, v1);
                        if (d < NOPE_) {
                            size_t o = ((size_t)(zb * NH_ + h) * S_LEN + s) * QK_ + d;
                            *reinterpret_cast<uint32_t*>(J.P1h + o) = hh;
                        } else {
                            size_t o = ((size_t)(zb * NH_ + h) * S_LEN + s) * VDIM_ + (d - NOPE_);
                            *reinterpret_cast<uint32_t*>(J.P2h + o) = hh;
                        }
                    }
                }
            }
        }
    }
}

// ---------------- fused flash attention (pure fp16 operands) --------------
__global__ void __launch_bounds__(256, 1)
flash_kernel(const f16* __restrict__ Qh,
             const f16* __restrict__ Kh,
             const f16* __restrict__ Vh,
             f16* __restrict__ Oh)
{
    extern __shared__ f16 fs[];
    f16* Qhs = fs;                       // 128 x QP
    f16* Khs = Qhs + 128 * QP;           // 64 x QP
    f16* Vst = Khs + 64 * QP;            // Vh0, Vh1 (64 x VP each)

    const int z = blockIdx.y, zb = z >> 4, zh = z & 15;
    const int mt = (int)gridDim.x - 1 - (int)blockIdx.x;
    const int m0 = mt * 128;
    const int tid = threadIdx.x, lane = tid & 31, warp = tid >> 5;
    const int g = lane >> 2, tg = lane & 3;
    const int wr = warp * 16;

    const uint32_t sQh = smem_u32(Qhs);
    const uint32_t sKh = smem_u32(Khs);
    const uint32_t sV0 = smem_u32(Vst);
    const uint32_t VSTRIDE = 64 * VP * 2;

    const size_t qzb = (size_t)z * S_LEN * QK_;
    const size_t vzb = (size_t)z * S_LEN * VDIM_;

    auto issue_K = [&](int k0) {
        for (int i = tid; i < 64 * 24; i += 256) {
            int r = i / 24, c = (i % 24) * 8;
            size_t go = qzb + (size_t)(k0 + r) * QK_ + c;
            uint32_t so = (uint32_t)((r * QP + c) * 2);
            cp_async16(sKh + so, Kh + go, 16);
        }
    };
    auto issue_V = [&](int k0, int stage) {
        uint32_t base = sV0 + (uint32_t)stage * VSTRIDE;
        for (int i = tid; i < 64 * 16; i += 256) {
            int r = i / 16, c = (i % 16) * 8;
            size_t go = vzb + (size_t)(k0 + r) * VDIM_ + c;
            uint32_t so = (uint32_t)((r * VP + c) * 2);
            cp_async16(base + so, Vh + go, 16);
        }
    };

    for (int i = tid; i < 128 * 24; i += 256) {
        int r = i / 24, c = (i % 24) * 8;
        size_t go = qzb + (size_t)(m0 + r) * QK_ + c;
        uint32_t so = (uint32_t)((r * QP + c) * 2);
        cp_async16(sQh + so, Qh + go, 16);
    }
    cp_commit();
    issue_K(0);  cp_commit();
    issue_V(0, 0); cp_commit();

    float mr0 = -1e30f, mr1 = -1e30f, lr0 = 0.f, lr1 = 0.f;
    float oacc[16][4];
    #pragma unroll
    for (int i = 0; i < 16; i++)
        #pragma unroll
        for (int j = 0; j < 4; j++) oacc[i][j] = 0.f;

    const int nkt = (m0 + 128) / 64;
    for (int kt = 0; kt < nkt; kt++) {
        const int k0 = kt * 64;
        const int cur = kt & 1;

        __syncthreads();                      // sync1: PV readers of stage cur^1 done
        if (kt + 1 < nkt) issue_V((kt + 1) * 64, cur ^ 1);
        cp_commit();
        if (kt + 1 < nkt) cp_wait<1>();
        else             cp_wait<0>();
        __syncthreads();                      // sync2

        float sacc[8][4];
        #pragma unroll
        for (int i = 0; i < 8; i++)
            #pragma unroll
            for (int j = 0; j < 4; j++) sacc[i][j] = 0.f;

        #pragma unroll
        for (int ks = 0; ks < 12; ks++) {
            uint32_t ah[4];
            uint32_t aoff = (uint32_t)(((wr + (lane & 15)) * QP + ks * 16 + (lane >> 4) * 8) * 2);
            ldsm4(ah, sQh + aoff);
            #pragma unroll
            for (int np = 0; np < 4; np++) {
                uint32_t kh4[4];
                uint32_t boff = (uint32_t)(((np * 16 + (lane & 15)) * QP + ks * 16 + (lane >> 4) * 8) * 2);
                ldsm4(kh4, sKh + boff);
                uint32_t b0h[2] = {kh4[0], kh4[2]}, b1h[2] = {kh4[1], kh4[3]};
                mma16816(sacc[2*np],   ah, b0h);
                mma16816(sacc[2*np+1], ah, b1h);
            }
        }

        __syncthreads();                      // sync3: K readers done
        if (kt + 1 < nkt) issue_K((kt + 1) * 64);
        cp_commit();

        if (k0 + 63 > m0) {
            int r0 = m0 + wr + g, r1 = r0 + 8;
            #pragma unroll
            for (int ni = 0; ni < 8; ni++) {
                int c0 = k0 + ni * 8 + 2 * tg;
                if (c0     > r0) sacc[ni][0] = -1e30f;
                if (c0 + 1 > r0) sacc[ni][1] = -1e30f;
                if (c0     > r1) sacc[ni][2] = -1e30f;
                if (c0 + 1 > r1) sacc[ni][3] = -1e30f;
            }
        }

        float mx0 = -1e30f, mx1 = -1e30f;
        #pragma unroll
        for (int ni = 0; ni < 8; ni++) {
            mx0 = fmaxf(mx0, fmaxf(sacc[ni][0], sacc[ni][1]));
            mx1 = fmaxf(mx1, fmaxf(sacc[ni][2], sacc[ni][3]));
        }
        mx0 = fmaxf(mx0, __shfl_xor_sync(0xffffffffu, mx0, 1));
        mx0 = fmaxf(mx0, __shfl_xor_sync(0xffffffffu, mx0, 2));
        mx1 = fmaxf(mx1, __shfl_xor_sync(0xffffffffu, mx1, 1));
        mx1 = fmaxf(mx1, __shfl_xor_sync(0xffffffffu, mx1, 2));
        float nm0 = fmaxf(mr0, mx0), nm1 = fmaxf(mr1, mx1);
        float al0 = __expf(mr0 - nm0), al1 = __expf(mr1 - nm1);
        mr0 = nm0; mr1 = nm1;
        float s0 = 0.f, s1 = 0.f;
        #pragma unroll
        for (int ni = 0; ni < 8; ni++) {
            sacc[ni][0] = __expf(sacc[ni][0] - nm0);
            sacc[ni][1] = __expf(sacc[ni][1] - nm0);
            sacc[ni][2] = __expf(sacc[ni][2] - nm1);
            sacc[ni][3] = __expf(sacc[ni][3] - nm1);
            s0 += sacc[ni][0] + sacc[ni][1];
            s1 += sacc[ni][2] + sacc[ni][3];
        }
        s0 += __shfl_xor_sync(0xffffffffu, s0, 1);
        s0 += __shfl_xor_sync(0xffffffffu, s0, 2);
        s1 += __shfl_xor_sync(0xffffffffu, s1, 1);
        s1 += __shfl_xor_sync(0xffffffffu, s1, 2);
        lr0 = lr0 * al0 + s0;
        lr1 = lr1 * al1 + s1;
        #pragma unroll
        for (int i = 0; i < 16; i++) {
            oacc[i][0] *= al0; oacc[i][1] *= al0;
            oacc[i][2] *= al1; oacc[i][3] *= al1;
        }

        const uint32_t sVh = sV0 + (uint32_t)cur * VSTRIDE;
        #pragma unroll
        for (int kk = 0; kk < 4; kk++) {
            uint32_t pah[4];
            pah[0] = pack2h(sacc[2*kk][0],   sacc[2*kk][1]);
            pah[1] = pack2h(sacc[2*kk][2],   sacc[2*kk][3]);
            pah[2] = pack2h(sacc[2*kk+1][0], sacc[2*kk+1][1]);
            pah[3] = pack2h(sacc[2*kk+1][2], sacc[2*kk+1][3]);
            #pragma unroll
            for (int np = 0; np < 8; np++) {
                uint32_t vh4[4];
                uint32_t voff = (uint32_t)(((kk * 16 + (lane & 15)) * VP + np * 16 + (lane >> 4) * 8) * 2);
                ldsm4t(vh4, sVh + voff);
                uint32_t bh0[2] = {vh4[0], vh4[1]}, bh1[2] = {vh4[2], vh4[3]};
                mma16816(oacc[2*np],   pah, bh0);
                mma16816(oacc[2*np+1], pah, bh1);
            }
        }
    }

    float i0 = 1.f / lr0, i1 = 1.f / lr1;
    size_t row0 = (size_t)(zb * S_LEN + m0 + wr + g) * DIM_ + zh * VDIM_;
    size_t row1 = row0 + (size_t)8 * DIM_;
    #pragma unroll
    for (int ni = 0; ni < 16; ni++) {
        int d = ni * 8 + 2 * tg;
        *reinterpret_cast<uint32_t*>(Oh + row0 + d) = pack2h(oacc[ni][0] * i0, oacc[ni][1] * i0);
        *reinterpret_cast<uint32_t*>(Oh + row1 + d) = pack2h(oacc[ni][2] * i1, oacc[ni][3] * i1);
    }
}

// ---------------- multi-segment fp32 -> fp16 convert ----------------
struct SplitJobs {
    const float* src[6];
    f16* hi[6];
    long long off[7];    // prefix offsets in float4 units (all even)
};
__global__ void __launch_bounds__(256)
split_multi_kernel(SplitJobs J)
{
    long long gidx = (long long)blockIdx.x * 256 + threadIdx.x;   // 2 float4 per thread
    if (gidx * 2 >= J.off[6]) return;
    long long idx = gidx * 2;
    int j = 0;
    #pragma unroll
    for (int t = 1; t < 6; t++) if (idx >= J.off[t]) j = t;
    long long i = idx - J.off[j];
    float4 v0 = reinterpret_cast<const float4*>(J.src[j])[i];
    float4 v1 = reinterpret_cast<const float4*>(J.src[j])[i + 1];
    union { f16 b[8]; uint4 u; } H;
    H.b[0] = __float2half_rn(v0.x); H.b[1] = __float2half_rn(v0.y);
    H.b[2] = __float2half_rn(v0.z); H.b[3] = __float2half_rn(v0.w);
    H.b[4] = __float2half_rn(v1.x); H.b[5] = __float2half_rn(v1.y);
    H.b[6] = __float2half_rn(v1.z); H.b[7] = __float2half_rn(v1.w);
    reinterpret_cast<uint4*>(J.hi[j])[i >> 1] = H.u;
}

// ---------------- merged RMSNorm (q rows then kv rows) -> fp16 -------------
__global__ void __launch_bounds__(256)
rmsnorm2_kernel(const float* __restrict__ qin, const float* __restrict__ qw,
                f16* __restrict__ qh,
                const float* __restrict__ kin, const float* __restrict__ kw,
                f16* __restrict__ kh)
{
    long long row = blockIdx.x;
    const float* p; const float* w; f16* oh; int n;
    if (row < M_ROWS) {
        p = qin + row * QL; w = qw; oh = qh + row * QL; n = QL;
    } else {
        row -= M_ROWS;
        p = kin + row * KVD_; w = kw; oh = kh + row * KVL; n = KVL;
    }
    float s = 0.f;
    for (int i = threadIdx.x; i < n; i += 256) { float v = p[i]; s += v * v; }
    __shared__ float red[256];
    red[threadIdx.x] = s; __syncthreads();
    for (int st = 128; st > 0; st >>= 1) {
        if (threadIdx.x < st) red[threadIdx.x] += red[threadIdx.x + st];
        __syncthreads();
    }
    float scale = rsqrtf(red[0] / (float)n + EPS_);
    for (int i = threadIdx.x; i < n; i += 256)
        oh[i] = __float2half_rn(p[i] * scale * w[i]);
}

// ---------------- K rope: rope(kvd cols 512..575) -> Kf cols 128..191 ------
__global__ void __launch_bounds__(256)
k_rope_kernel(const float* __restrict__ kvd, const float* __restrict__ freqs,
              f16* __restrict__ Kfh)
{
    int idx = blockIdx.x * 256 + threadIdx.x;
    const int total = M_ROWS * (ROPE_D / 2);
    if (idx >= total) return;
    int dp = idx % (ROPE_D / 2);
    int m  = idx / (ROPE_D / 2);
    int s  = m & (S_LEN - 1);
    int zb = m >> 11;
    float f = freqs[s * (ROPE_D / 2) + dp];
    float c = cosf(f), sn = sinf(f);
    float x0 = kvd[(size_t)m * KVD_ + KVL + 2 * dp];
    float x1 = kvd[(size_t)m * KVD_ + KVL + 2 * dp + 1];
    float y0 = x0 * c - x1 * sn;
    float y1 = x0 * sn + x1 * c;
    uint32_t hh = pack2h(y0, y1);
    #pragma unroll
    for (int h = 0; h < NH_; h++) {
        size_t o = ((size_t)(zb * NH_ + h) * S_LEN + s) * QK_ + NOPE_ + 2 * dp;
        *reinterpret_cast<uint32_t*>(Kfh + o) = hh;
    }
}

// ---------------- host ----------------
extern "C" void kernel_launch(void* const* d_in, const int* in_sizes, int n_in,
                              void* d_out, int out_size)
{
    (void)in_sizes; (void)n_in; (void)out_size;
    const float* x        = (const float*)d_in[0];
    const float* freqs    = (const float*)d_in[1];
    const float* Wq_down  = (const float*)d_in[3];
    const float* bq_down  = (const float*)d_in[4];
    const float* q_norm   = (const float*)d_in[5];
    const float* Wq_up    = (const float*)d_in[6];
    const float* bq_up    = (const float*)d_in[7];
    const float* Wkv_down = (const float*)d_in[8];
    const float* bkv_down = (const float*)d_in[9];
    const float* kv_norm  = (const float*)d_in[10];
    const float* Wkv_up   = (const float*)d_in[11];
    const float* bkv_up   = (const float*)d_in[12];
    const float* Wo       = (const float*)d_in[13];
    const float* bo       = (const float*)d_in[14];
    float* out = (float*)d_out;

    void* p;
    #define SYM(var, sym, T) cudaGetSymbolAddress(&p, sym); T* var = (T*)p
    SYM(qmid,  g_qmid,  float);  SYM(kvd,   g_kvd,   float);
    SYM(xh,  g_xh,  f16);
    SYM(qlh, g_qlh, f16); SYM(klh, g_klh, f16);
    SYM(Qzh, g_Qzh, f16);
    SYM(Kfh, g_Kfh, f16); SYM(Vzh, g_Vzh, f16);
    SYM(Oh,  g_Oh,  f16);
    SYM(Wqdh, g_Wqdh, f16); SYM(Wquh, g_Wquh, f16);
    SYM(Wkdh, g_Wkdh, f16); SYM(Wkuh, g_Wkuh, f16);
    SYM(Woh,  g_Woh,  f16);
    #undef SYM

    const float scale = 1.0f / sqrtf((float)QK_);
    // Q 128xQP + K 64xQP + V double-buffered 2x64xVP
    const int FLASH_SMEM = (128 * QP + 64 * QP + 2 * 64 * VP) * 2;  // 111616 B
    cudaFuncSetAttribute(flash_kernel, cudaFuncAttributeMaxDynamicSharedMemorySize, FLASH_SMEM);

    // 0) all fp32->fp16 conversions in one launch
    SplitJobs SJ;
    SJ.src[0] = x;        SJ.hi[0] = xh;
    SJ.src[1] = Wq_down;  SJ.hi[1] = Wqdh;
    SJ.src[2] = Wq_up;    SJ.hi[2] = Wquh;
    SJ.src[3] = Wkv_down; SJ.hi[3] = Wkdh;
    SJ.src[4] = Wkv_up;   SJ.hi[4] = Wkuh;
    SJ.src[5] = Wo;       SJ.hi[5] = Woh;
    long long n4s[6] = {
        (long long)M_ROWS*DIM_/4, (long long)QL*DIM_/4, (long long)NQK*QL/4,
        (long long)KVD_*DIM_/4,   (long long)NKV*KVL/4, (long long)DIM_*DIM_/4 };
    SJ.off[0] = 0;
    for (int i = 0; i < 6; i++) SJ.off[i+1] = SJ.off[i] + n4s[i];
    long long ngroups = SJ.off[6] / 2;
    split_multi_kernel<<<(int)((ngroups + 255) / 256), 256>>>(SJ);

    auto mkjob = [](const f16* Ah, const f16* Bh,
                    const float* bias, float* C,
                    f16* P1h, f16* P2h,
                    int N, int K, int lda, int ldb, int ldc, int epi, int tile_off) {
        GemmJob j;
        j.Ah = Ah; j.Bh = Bh; j.bias = bias; j.C = C;
        j.P1h = P1h; j.P2h = P2h;
        j.N = N; j.K = K; j.lda = lda; j.ldb = ldb; j.ldc = ldc;
        j.ntx = (N + 127) / 128; j.epi = epi; j.tile_off = tile_off;
        return j;
    };

    // 1) merged down-projections: q_mid (384 tiles) + kvd (160 tiles)
    {
        GemmJobs JB;
        JB.njobs = 2; JB.freqs = freqs; JB.scale = scale;
        JB.j[0] = mkjob(xh, Wqdh, bq_down, qmid, nullptr, nullptr,
                        QL, DIM_, DIM_, DIM_, QL, 0, 0);
        int t0 = (QL/128) * (M_ROWS/128);
        JB.j[1] = mkjob(xh, Wkdh, bkv_down, kvd, nullptr, nullptr,
                        KVD_, DIM_, DIM_, DIM_, KVD_, 0, t0);
        int total = t0 + ((KVD_+127)/128) * (M_ROWS/128);
        mma_gemm_multi<<<total, 256>>>(JB);
    }
    // 2) merged rmsnorm -> fp16
    rmsnorm2_kernel<<<2 * M_ROWS, 256>>>(qmid, q_norm, qlh, kvd, kv_norm, klh);
    // 3) K rope -> Kf cols 128..191
    k_rope_kernel<<<(M_ROWS*(ROPE_D/2) + 255)/256, 256>>>(kvd, freqs, Kfh);
    // 4) merged up-projections: Q (768 tiles, EPI1) + KV (1024 tiles, EPI2)
    {
        GemmJobs JB;
        JB.njobs = 2; JB.freqs = freqs; JB.scale = scale;
        JB.j[0] = mkjob(qlh, Wquh, bq_up, nullptr, Qzh, nullptr,
                        NQK, QL, QL, QL, NQK, 1, 0);
        int t0 = (NQK/128) * (M_ROWS/128);
        JB.j[1] = mkjob(klh, Wkuh, bkv_up, nullptr, Kfh, Vzh,
                        NKV, KVL, KVL, KVL, NKV, 2, t0);
        int total = t0 + (NKV/128) * (M_ROWS/128);
        mma_gemm_multi<<<total, 256>>>(JB);
    }
    // 5) pipelined flash attention -> Oh
    flash_kernel<<<dim3(16, BATCH*NH_), 256, FLASH_SMEM>>>(Qzh, Kfh, Vzh, Oh);
    // 6) out = O @ Wo^T + b
    {
        GemmJobs JB;
        JB.njobs = 1; JB.freqs = freqs; JB.scale = scale;
        JB.j[0] = mkjob(Oh, Woh, bo, out, nullptr, nullptr,
                        DIM_, NH_*VDIM_, NH_*VDIM_, NH_*VDIM_, DIM_, 0, 0);
        mma_gemm_multi<<<(DIM_/128) * (M_ROWS/128), 256>>>(JB);
    }
}